// round 2
// baseline (speedup 1.0000x reference)
#include <cuda_runtime.h>
#include <cstdint>

#define NBLK 128
#define THREADS 256

// ---------------- device globals (scratch; no cudaMalloc allowed) ----------
__device__ float g_x[256 * 256 * 64];          // x, tf32-rounded
__device__ float g_Bp0[16 * 576 * 128];        // layer0 weights, prepacked [strip][k][col]
__device__ float g_Bp1[16 * 1024 * 128];       // layer1 weights, prepacked
__device__ float g_bias0[16 * 128];
__device__ float g_bias1[16 * 128];
__device__ float g_h0[2][256 * 512];           // layer0 hidden, double buffered (tf32)
__device__ float g_h1[2][256 * 512];           // layer1 hidden, double buffered (tf32)
__device__ float g_h1x[256 * 512];             // layer1 hidden, exact fp32 (for FC)
__device__ unsigned g_count;
__device__ unsigned g_phase;

// ---------------- helpers ---------------------------------------------------
__device__ __forceinline__ float tf32r(float x) {
    unsigned u;
    asm("cvt.rna.tf32.f32 %0, %1;" : "=r"(u) : "f"(x));
    return __uint_as_float(u);
}

__device__ __forceinline__ void cpa_cg(float* dst, const float* src) {
    unsigned s = (unsigned)__cvta_generic_to_shared(dst);
    asm volatile("cp.async.cg.shared.global [%0], [%1], 16;" :: "r"(s), "l"(src));
}
__device__ __forceinline__ void cpa_ca(float* dst, const float* src) {
    unsigned s = (unsigned)__cvta_generic_to_shared(dst);
    asm volatile("cp.async.ca.shared.global [%0], [%1], 16;" :: "r"(s), "l"(src));
}
#define CP_COMMIT asm volatile("cp.async.commit_group;")
#define CP_WAIT1  asm volatile("cp.async.wait_group 1;")
#define CP_WAIT0  asm volatile("cp.async.wait_group 0;")

__device__ __forceinline__ void mma8(float* c, const unsigned* a, const unsigned* b) {
    asm volatile(
        "mma.sync.aligned.m16n8k8.row.col.f32.tf32.tf32.f32 "
        "{%0,%1,%2,%3},{%4,%5,%6,%7},{%8,%9},{%0,%1,%2,%3};"
        : "+f"(c[0]), "+f"(c[1]), "+f"(c[2]), "+f"(c[3])
        : "r"(a[0]), "r"(a[1]), "r"(a[2]), "r"(a[3]), "r"(b[0]), "r"(b[1]));
}

// ---------------- prep kernels ----------------------------------------------
__global__ void prep_x(const float* __restrict__ x) {
    int idx = blockIdx.x * blockDim.x + threadIdx.x;
    if (idx < 256 * 256 * 64) g_x[idx] = tf32r(x[idx]);
}

// layout: Bp[strip][k][c], c = 4*hl + gate, row = gate*512 + strip*32 + hl
__global__ void prep_w0(const float* __restrict__ Wih, const float* __restrict__ Whh) {
    int idx = blockIdx.x * blockDim.x + threadIdx.x;
    if (idx >= 16 * 576 * 128) return;
    int c = idx & 127;
    int k = (idx >> 7) % 576;
    int sst = idx / (576 * 128);
    int g = c & 3, hl = c >> 2;
    int row = g * 512 + sst * 32 + hl;
    float v = (k < 64) ? Wih[row * 64 + k] : Whh[row * 512 + (k - 64)];
    g_Bp0[idx] = tf32r(v);
}
__global__ void prep_w1(const float* __restrict__ Wih, const float* __restrict__ Whh) {
    int idx = blockIdx.x * blockDim.x + threadIdx.x;
    if (idx >= 16 * 1024 * 128) return;
    int c = idx & 127;
    int k = (idx >> 7) & 1023;
    int sst = idx >> 17;
    int g = c & 3, hl = c >> 2;
    int row = g * 512 + sst * 32 + hl;
    float v = (k < 512) ? Wih[row * 512 + k] : Whh[row * 512 + (k - 512)];
    g_Bp1[idx] = tf32r(v);
}
__global__ void prep_bias(const float* __restrict__ bi0, const float* __restrict__ bh0,
                          const float* __restrict__ bi1, const float* __restrict__ bh1) {
    int idx = blockIdx.x * blockDim.x + threadIdx.x;
    if (idx >= 2 * 2048) return;
    int l = idx >> 11;
    int rr = idx & 2047;
    int c = rr & 127, sst = rr >> 7;
    int g = c & 3, hl = c >> 2;
    int row = g * 512 + sst * 32 + hl;
    float v = l ? (bi1[row] + bh1[row]) : (bi0[row] + bh0[row]);
    (l ? g_bias1 : g_bias0)[rr] = v;
}
__global__ void prep_zero() {
    int idx = blockIdx.x * blockDim.x + threadIdx.x;
    float* p0 = &g_h0[0][0];
    float* p1 = &g_h1[0][0];
    if (idx < 2 * 256 * 512) { p0[idx] = 0.f; p1[idx] = 0.f; }
    if (idx == 0) { g_count = 0u; g_phase = 0u; }
}

// ---------------- tile loads --------------------------------------------
__device__ __forceinline__ void load_tiles(int layer, int s, int m0, int rp,
                                           const float* __restrict__ bp, int k0,
                                           float* As, float* Bs, int tid) {
    const float* abase;
    int astride;
    if (layer == 0) {
        if (k0 < 64) { abase = g_x + (size_t)m0 * 16384 + s * 64 + k0; astride = 16384; }
        else         { abase = g_h0[rp] + m0 * 512 + (k0 - 64);        astride = 512; }
    } else {
        if (k0 < 512) { abase = g_h0[rp] + m0 * 512 + k0;         astride = 512; }
        else          { abase = g_h1[rp] + m0 * 512 + (k0 - 512); astride = 512; }
    }
#pragma unroll
    for (int i = 0; i < 2; i++) {   // A: 64 rows x 32 floats = 512 float4
        int ch = tid + THREADS * i;
        int row = ch >> 3, seg = ch & 7;
        cpa_cg(&As[row * 36 + seg * 4], abase + (size_t)row * astride + seg * 4);
    }
    const float* bbase = bp + (size_t)k0 * 128;
#pragma unroll
    for (int i = 0; i < 4; i++) {   // B: 32 rows x 128 floats = 1024 float4
        int ch = tid + THREADS * i;
        int row = ch >> 5, seg = ch & 31;
        cpa_ca(&Bs[row * 132 + seg * 4], bbase + row * 128 + seg * 4);
    }
}

// ---------------- persistent LSTM kernel ------------------------------------
__global__ __launch_bounds__(THREADS, 1)
void lstm_persistent(const float* __restrict__ Wfc, const float* __restrict__ bfc,
                     float* __restrict__ out) {
    extern __shared__ float dsm[];
    float* As[2] = { dsm, dsm + 2304 };            // 64 x 36
    float* Bs[2] = { dsm + 4608, dsm + 8832 };     // 32 x 132
    __shared__ float bias_s[128];

    const int tid   = threadIdx.x;
    const int lane  = tid & 31;
    const int warp  = tid >> 5;
    const int warpM = warp >> 2;   // 0..1 -> 32-row block
    const int warpN = warp & 3;    // 0..3 -> 32-col block
    const int bid   = blockIdx.x;
    const int layer = bid >> 6;
    const int tile  = bid & 63;
    const int m0    = (tile & 3) * 64;
    const int strip = tile >> 2;
    const int ktiles = layer ? 32 : 18;
    const float* bp    = layer ? (g_Bp1 + (size_t)strip * 1024 * 128)
                               : (g_Bp0 + (size_t)strip * 576 * 128);
    const float* biasg = (layer ? g_bias1 : g_bias0) + strip * 128;

    for (int i = tid; i < 128; i += THREADS) bias_s[i] = biasg[i];
    __syncthreads();

    float cst[8];
#pragma unroll
    for (int j = 0; j < 8; j++) cst[j] = 0.f;

    unsigned target = 0;

    for (int s = 0; s <= 256; s++) {
        bool active = layer ? (s >= 1) : (s < 256);
        if (active) {
            const int rp = (s + 1) & 1;   // parity of step s-1 (read buffers)
            float acc[2][4][4];
#pragma unroll
            for (int mi = 0; mi < 2; mi++)
#pragma unroll
                for (int ni = 0; ni < 4; ni++)
#pragma unroll
                    for (int q = 0; q < 4; q++) acc[mi][ni][q] = 0.f;

            load_tiles(layer, s, m0, rp, bp, 0, As[0], Bs[0], tid);
            CP_COMMIT;

            for (int kt = 0; kt < ktiles; kt++) {
                if (kt + 1 < ktiles) {
                    load_tiles(layer, s, m0, rp, bp, (kt + 1) * 32,
                               As[(kt + 1) & 1], Bs[(kt + 1) & 1], tid);
                    CP_COMMIT;
                    CP_WAIT1;
                } else {
                    CP_WAIT0;
                }
                __syncthreads();

                const float* as = As[kt & 1];
                const float* bs = Bs[kt & 1];
#pragma unroll
                for (int kk = 0; kk < 4; kk++) {
                    unsigned afr[2][4], bfr[4][2];
#pragma unroll
                    for (int mi = 0; mi < 2; mi++) {
                        int rb = warpM * 32 + mi * 16 + (lane >> 2);
                        int cb = kk * 8 + (lane & 3);
                        afr[mi][0] = __float_as_uint(as[rb * 36 + cb]);
                        afr[mi][1] = __float_as_uint(as[(rb + 8) * 36 + cb]);
                        afr[mi][2] = __float_as_uint(as[rb * 36 + cb + 4]);
                        afr[mi][3] = __float_as_uint(as[(rb + 8) * 36 + cb + 4]);
                    }
#pragma unroll
                    for (int ni = 0; ni < 4; ni++) {
                        int nb = warpN * 32 + ni * 8 + (lane >> 2);
                        int kb = kk * 8 + (lane & 3);
                        bfr[ni][0] = __float_as_uint(bs[kb * 132 + nb]);
                        bfr[ni][1] = __float_as_uint(bs[(kb + 4) * 132 + nb]);
                    }
#pragma unroll
                    for (int mi = 0; mi < 2; mi++)
#pragma unroll
                        for (int ni = 0; ni < 4; ni++)
                            mma8(acc[mi][ni], afr[mi], bfr[ni]);
                }
                __syncthreads();
            }

            // gates -> smem (reuse stage buffers), then pointwise LSTM cell
            float* Gs = dsm;   // [64][132]
#pragma unroll
            for (int mi = 0; mi < 2; mi++) {
                int rr = warpM * 32 + mi * 16 + (lane >> 2);
#pragma unroll
                for (int ni = 0; ni < 4; ni++) {
                    int cc = warpN * 32 + ni * 8 + (lane & 3) * 2;
                    Gs[rr * 132 + cc]           = acc[mi][ni][0];
                    Gs[rr * 132 + cc + 1]       = acc[mi][ni][1];
                    Gs[(rr + 8) * 132 + cc]     = acc[mi][ni][2];
                    Gs[(rr + 8) * 132 + cc + 1] = acc[mi][ni][3];
                }
            }
            __syncthreads();

            int r = tid >> 2;
            int hl0 = (tid & 3) * 8;
            float* hout = layer ? g_h1[s & 1] : g_h0[s & 1];
            int grow = m0 + r;
#pragma unroll
            for (int j = 0; j < 8; j++) {
                int c4 = (hl0 + j) * 4;
                float ip = Gs[r * 132 + c4 + 0] + bias_s[c4 + 0];
                float fp = Gs[r * 132 + c4 + 1] + bias_s[c4 + 1];
                float gp = Gs[r * 132 + c4 + 2] + bias_s[c4 + 2];
                float op = Gs[r * 132 + c4 + 3] + bias_s[c4 + 3];
                float ig = 1.f / (1.f + __expf(-ip));
                float fg = 1.f / (1.f + __expf(-fp));
                float gg = tanhf(gp);
                float og = 1.f / (1.f + __expf(-op));
                float cn = fg * cst[j] + ig * gg;
                cst[j] = cn;
                float h = og * tanhf(cn);
                int idx = grow * 512 + strip * 32 + hl0 + j;
                hout[idx] = tf32r(h);
                if (layer) g_h1x[idx] = h;
            }
        }

        // ---- grid barrier (monotonic count/phase) ----
        target++;
        __threadfence();
        __syncthreads();
        if (tid == 0) {
            unsigned arrived = atomicAdd(&g_count, 1u) + 1u;
            if ((arrived & (NBLK - 1)) == 0u) {
                atomicAdd(&g_phase, 1u);
            } else {
                while (*((volatile unsigned*)&g_phase) < target) { }
            }
            __threadfence();
        }
        __syncthreads();
    }

    // ---- final FC: out[b] = h1x[b,:] . Wfc + bfc ----
    float* red = dsm;
    for (int r2 = 0; r2 < 2; r2++) {
        int b = bid * 2 + r2;
        float p = 0.f;
        for (int k = tid; k < 512; k += THREADS)
            p += __ldcg(&g_h1x[b * 512 + k]) * __ldg(&Wfc[k]);
        red[tid] = p;
        __syncthreads();
        for (int off = 128; off > 0; off >>= 1) {
            if (tid < off) red[tid] += red[tid + off];
            __syncthreads();
        }
        if (tid == 0) out[b] = red[0] + __ldg(bfc);
        __syncthreads();
    }
}

// ---------------- launch -----------------------------------------------------
extern "C" void kernel_launch(void* const* d_in, const int* in_sizes, int n_in,
                              void* d_out, int out_size) {
    const float* x    = (const float*)d_in[0];
    const float* Wih0 = (const float*)d_in[1];
    const float* Whh0 = (const float*)d_in[2];
    const float* bih0 = (const float*)d_in[3];
    const float* bhh0 = (const float*)d_in[4];
    const float* Wih1 = (const float*)d_in[5];
    const float* Whh1 = (const float*)d_in[6];
    const float* bih1 = (const float*)d_in[7];
    const float* bhh1 = (const float*)d_in[8];
    const float* Wfc  = (const float*)d_in[9];
    const float* bfc  = (const float*)d_in[10];
    float* out = (float*)d_out;

    cudaFuncSetAttribute(lstm_persistent,
                         cudaFuncAttributeMaxDynamicSharedMemorySize, 53248);

    prep_x<<<(256 * 256 * 64 + 255) / 256, 256>>>(x);
    prep_w0<<<(16 * 576 * 128 + 255) / 256, 256>>>(Wih0, Whh0);
    prep_w1<<<(16 * 1024 * 128 + 255) / 256, 256>>>(Wih1, Whh1);
    prep_bias<<<(4096 + 255) / 256, 256>>>(bih0, bhh0, bih1, bhh1);
    prep_zero<<<(2 * 256 * 512 + 255) / 256, 256>>>();
    lstm_persistent<<<NBLK, THREADS, 53248>>>(Wfc, bfc, out);
}

// round 3
// speedup vs baseline: 1.0126x; 1.0126x over previous
#include <cuda_runtime.h>
#include <cstdint>

#define NBLK 128
#define THREADS 256

// ---------------- device globals (scratch; no cudaMalloc allowed) ----------
__device__ float g_x[256 * 256 * 64];          // x, tf32-rounded
__device__ float g_Bp0[16 * 576 * 128];        // layer0 weights, prepacked [strip][k][col]
__device__ float g_Bp1[16 * 1024 * 128];       // layer1 weights, prepacked
__device__ float g_bias0[16 * 128];
__device__ float g_bias1[16 * 128];
__device__ float g_h0[2][256 * 512];           // layer0 hidden, double buffered (tf32)
__device__ float g_h1[2][256 * 512];           // layer1 hidden, double buffered (tf32)
__device__ float g_h1x[256 * 512];             // layer1 hidden, exact fp32 (for FC)
__device__ unsigned g_count;
__device__ unsigned g_phase;

// ---------------- helpers ---------------------------------------------------
__device__ __forceinline__ float tf32r(float x) {
    unsigned u;
    asm("cvt.rna.tf32.f32 %0, %1;" : "=r"(u) : "f"(x));
    return __uint_as_float(u);
}

__device__ __forceinline__ void cpa_cg(float* dst, const float* src) {
    unsigned s = (unsigned)__cvta_generic_to_shared(dst);
    asm volatile("cp.async.cg.shared.global [%0], [%1], 16;" :: "r"(s), "l"(src));
}
__device__ __forceinline__ void cpa_ca(float* dst, const float* src) {
    unsigned s = (unsigned)__cvta_generic_to_shared(dst);
    asm volatile("cp.async.ca.shared.global [%0], [%1], 16;" :: "r"(s), "l"(src));
}
#define CP_COMMIT asm volatile("cp.async.commit_group;")
#define CP_WAIT1  asm volatile("cp.async.wait_group 1;")
#define CP_WAIT0  asm volatile("cp.async.wait_group 0;")

__device__ __forceinline__ void mma8(float* c, const unsigned* a, const unsigned* b) {
    asm volatile(
        "mma.sync.aligned.m16n8k8.row.col.f32.tf32.tf32.f32 "
        "{%0,%1,%2,%3},{%4,%5,%6,%7},{%8,%9},{%0,%1,%2,%3};"
        : "+f"(c[0]), "+f"(c[1]), "+f"(c[2]), "+f"(c[3])
        : "r"(a[0]), "r"(a[1]), "r"(a[2]), "r"(a[3]), "r"(b[0]), "r"(b[1]));
}

// ---------------- prep kernels ----------------------------------------------
__global__ void prep_x(const float* __restrict__ x) {
    int idx = blockIdx.x * blockDim.x + threadIdx.x;
    if (idx < 256 * 256 * 64) g_x[idx] = tf32r(x[idx]);
}

// layout: Bp[strip][k][c], c = 4*hl + gate, row = gate*512 + strip*32 + hl
__global__ void prep_w0(const float* __restrict__ Wih, const float* __restrict__ Whh) {
    int idx = blockIdx.x * blockDim.x + threadIdx.x;
    if (idx >= 16 * 576 * 128) return;
    int c = idx & 127;
    int k = (idx >> 7) % 576;
    int sst = idx / (576 * 128);
    int g = c & 3, hl = c >> 2;
    int row = g * 512 + sst * 32 + hl;
    float v = (k < 64) ? Wih[row * 64 + k] : Whh[row * 512 + (k - 64)];
    g_Bp0[idx] = tf32r(v);
}
__global__ void prep_w1(const float* __restrict__ Wih, const float* __restrict__ Whh) {
    int idx = blockIdx.x * blockDim.x + threadIdx.x;
    if (idx >= 16 * 1024 * 128) return;
    int c = idx & 127;
    int k = (idx >> 7) & 1023;
    int sst = idx >> 17;
    int g = c & 3, hl = c >> 2;
    int row = g * 512 + sst * 32 + hl;
    float v = (k < 512) ? Wih[row * 512 + k] : Whh[row * 512 + (k - 512)];
    g_Bp1[idx] = tf32r(v);
}
__global__ void prep_bias(const float* __restrict__ bi0, const float* __restrict__ bh0,
                          const float* __restrict__ bi1, const float* __restrict__ bh1) {
    int idx = blockIdx.x * blockDim.x + threadIdx.x;
    if (idx >= 2 * 2048) return;
    int l = idx >> 11;
    int rr = idx & 2047;
    int c = rr & 127, sst = rr >> 7;
    int g = c & 3, hl = c >> 2;
    int row = g * 512 + sst * 32 + hl;
    float v = l ? (bi1[row] + bh1[row]) : (bi0[row] + bh0[row]);
    (l ? g_bias1 : g_bias0)[rr] = v;
}
__global__ void prep_zero() {
    int idx = blockIdx.x * blockDim.x + threadIdx.x;
    float* p0 = &g_h0[0][0];
    float* p1 = &g_h1[0][0];
    if (idx < 2 * 256 * 512) { p0[idx] = 0.f; p1[idx] = 0.f; }
    if (idx == 0) { g_count = 0u; g_phase = 0u; }
}

// ---------------- tile loads --------------------------------------------
__device__ __forceinline__ void load_tiles(int layer, int s, int m0, int rp,
                                           const float* __restrict__ bp, int k0,
                                           float* As, float* Bs, int tid) {
    const float* abase;
    int astride;
    if (layer == 0) {
        if (k0 < 64) { abase = g_x + (size_t)m0 * 16384 + s * 64 + k0; astride = 16384; }
        else         { abase = g_h0[rp] + m0 * 512 + (k0 - 64);        astride = 512; }
    } else {
        if (k0 < 512) { abase = g_h0[rp] + m0 * 512 + k0;         astride = 512; }
        else          { abase = g_h1[rp] + m0 * 512 + (k0 - 512); astride = 512; }
    }
#pragma unroll
    for (int i = 0; i < 2; i++) {   // A: 64 rows x 32 floats = 512 float4
        int ch = tid + THREADS * i;
        int row = ch >> 3, seg = ch & 7;
        cpa_cg(&As[row * 36 + seg * 4], abase + (size_t)row * astride + seg * 4);
    }
    const float* bbase = bp + (size_t)k0 * 128;
#pragma unroll
    for (int i = 0; i < 4; i++) {   // B: 32 rows x 128 floats = 1024 float4
        int ch = tid + THREADS * i;
        int row = ch >> 5, seg = ch & 31;
        cpa_ca(&Bs[row * 132 + seg * 4], bbase + row * 128 + seg * 4);
    }
}

// ---------------- persistent LSTM kernel ------------------------------------
__global__ __launch_bounds__(THREADS, 1)
void lstm_persistent(const float* __restrict__ Wfc, const float* __restrict__ bfc,
                     float* __restrict__ out) {
    extern __shared__ float dsm[];
    float* As[2] = { dsm, dsm + 2304 };            // 64 x 36
    float* Bs[2] = { dsm + 4608, dsm + 8832 };     // 32 x 132
    __shared__ float bias_s[128];

    const int tid   = threadIdx.x;
    const int lane  = tid & 31;
    const int warp  = tid >> 5;
    const int warpM = warp >> 2;   // 0..1 -> 32-row block
    const int warpN = warp & 3;    // 0..3 -> 32-col block
    const int bid   = blockIdx.x;
    const int layer = bid >> 6;
    const int tile  = bid & 63;
    const int m0    = (tile & 3) * 64;
    const int strip = tile >> 2;
    const int ktiles = layer ? 32 : 18;
    const float* bp    = layer ? (g_Bp1 + (size_t)strip * 1024 * 128)
                               : (g_Bp0 + (size_t)strip * 576 * 128);
    const float* biasg = (layer ? g_bias1 : g_bias0) + strip * 128;

    for (int i = tid; i < 128; i += THREADS) bias_s[i] = biasg[i];
    __syncthreads();

    float cst[8];
#pragma unroll
    for (int j = 0; j < 8; j++) cst[j] = 0.f;

    unsigned target = 0;

    for (int s = 0; s <= 256; s++) {
        bool active = layer ? (s >= 1) : (s < 256);
        if (active) {
            const int rp = (s + 1) & 1;   // parity of step s-1 (read buffers)
            float acc[2][4][4];
#pragma unroll
            for (int mi = 0; mi < 2; mi++)
#pragma unroll
                for (int ni = 0; ni < 4; ni++)
#pragma unroll
                    for (int q = 0; q < 4; q++) acc[mi][ni][q] = 0.f;

            load_tiles(layer, s, m0, rp, bp, 0, As[0], Bs[0], tid);
            CP_COMMIT;

            for (int kt = 0; kt < ktiles; kt++) {
                if (kt + 1 < ktiles) {
                    load_tiles(layer, s, m0, rp, bp, (kt + 1) * 32,
                               As[(kt + 1) & 1], Bs[(kt + 1) & 1], tid);
                    CP_COMMIT;
                    CP_WAIT1;
                } else {
                    CP_WAIT0;
                }
                __syncthreads();

                const float* as = As[kt & 1];
                const float* bs = Bs[kt & 1];
#pragma unroll
                for (int kk = 0; kk < 4; kk++) {
                    unsigned afr[2][4], bfr[4][2];
#pragma unroll
                    for (int mi = 0; mi < 2; mi++) {
                        int rb = warpM * 32 + mi * 16 + (lane >> 2);
                        int cb = kk * 8 + (lane & 3);
                        afr[mi][0] = __float_as_uint(as[rb * 36 + cb]);
                        afr[mi][1] = __float_as_uint(as[(rb + 8) * 36 + cb]);
                        afr[mi][2] = __float_as_uint(as[rb * 36 + cb + 4]);
                        afr[mi][3] = __float_as_uint(as[(rb + 8) * 36 + cb + 4]);
                    }
#pragma unroll
                    for (int ni = 0; ni < 4; ni++) {
                        int nb = warpN * 32 + ni * 8 + (lane >> 2);
                        int kb = kk * 8 + (lane & 3);
                        bfr[ni][0] = __float_as_uint(bs[kb * 132 + nb]);
                        bfr[ni][1] = __float_as_uint(bs[(kb + 4) * 132 + nb]);
                    }
#pragma unroll
                    for (int mi = 0; mi < 2; mi++)
#pragma unroll
                        for (int ni = 0; ni < 4; ni++)
                            mma8(acc[mi][ni], afr[mi], bfr[ni]);
                }
                __syncthreads();
            }

            // gates -> smem (reuse stage buffers), then pointwise LSTM cell
            float* Gs = dsm;   // [64][132]
#pragma unroll
            for (int mi = 0; mi < 2; mi++) {
                int rr = warpM * 32 + mi * 16 + (lane >> 2);
#pragma unroll
                for (int ni = 0; ni < 4; ni++) {
                    int cc = warpN * 32 + ni * 8 + (lane & 3) * 2;
                    Gs[rr * 132 + cc]           = acc[mi][ni][0];
                    Gs[rr * 132 + cc + 1]       = acc[mi][ni][1];
                    Gs[(rr + 8) * 132 + cc]     = acc[mi][ni][2];
                    Gs[(rr + 8) * 132 + cc + 1] = acc[mi][ni][3];
                }
            }
            __syncthreads();

            int r = tid >> 2;
            int hl0 = (tid & 3) * 8;
            float* hout = layer ? g_h1[s & 1] : g_h0[s & 1];
            int grow = m0 + r;
#pragma unroll
            for (int j = 0; j < 8; j++) {
                int c4 = (hl0 + j) * 4;
                float ip = Gs[r * 132 + c4 + 0] + bias_s[c4 + 0];
                float fp = Gs[r * 132 + c4 + 1] + bias_s[c4 + 1];
                float gp = Gs[r * 132 + c4 + 2] + bias_s[c4 + 2];
                float op = Gs[r * 132 + c4 + 3] + bias_s[c4 + 3];
                float ig = 1.f / (1.f + __expf(-ip));
                float fg = 1.f / (1.f + __expf(-fp));
                float gg = tanhf(gp);
                float og = 1.f / (1.f + __expf(-op));
                float cn = fg * cst[j] + ig * gg;
                cst[j] = cn;
                float h = og * tanhf(cn);
                int idx = grow * 512 + strip * 32 + hl0 + j;
                hout[idx] = tf32r(h);
                if (layer) g_h1x[idx] = h;
            }
        }

        // ---- grid barrier (monotonic count/phase) ----
        target++;
        __threadfence();
        __syncthreads();
        if (tid == 0) {
            unsigned arrived = atomicAdd(&g_count, 1u) + 1u;
            if ((arrived & (NBLK - 1)) == 0u) {
                atomicAdd(&g_phase, 1u);
            } else {
                while (*((volatile unsigned*)&g_phase) < target) { }
            }
            __threadfence();
        }
        __syncthreads();
    }

    // ---- final FC: out[b] = h1x[b,:] . Wfc + bfc ----
    float* red = dsm;
    for (int r2 = 0; r2 < 2; r2++) {
        int b = bid * 2 + r2;
        float p = 0.f;
        for (int k = tid; k < 512; k += THREADS)
            p += __ldcg(&g_h1x[b * 512 + k]) * __ldg(&Wfc[k]);
        red[tid] = p;
        __syncthreads();
        for (int off = 128; off > 0; off >>= 1) {
            if (tid < off) red[tid] += red[tid + off];
            __syncthreads();
        }
        if (tid == 0) out[b] = red[0] + __ldg(bfc);
        __syncthreads();
    }
}

// ---------------- launch -----------------------------------------------------
extern "C" void kernel_launch(void* const* d_in, const int* in_sizes, int n_in,
                              void* d_out, int out_size) {
    const float* x    = (const float*)d_in[0];
    const float* Wih0 = (const float*)d_in[1];
    const float* Whh0 = (const float*)d_in[2];
    const float* bih0 = (const float*)d_in[3];
    const float* bhh0 = (const float*)d_in[4];
    const float* Wih1 = (const float*)d_in[5];
    const float* Whh1 = (const float*)d_in[6];
    const float* bih1 = (const float*)d_in[7];
    const float* bhh1 = (const float*)d_in[8];
    const float* Wfc  = (const float*)d_in[9];
    const float* bfc  = (const float*)d_in[10];
    float* out = (float*)d_out;

    cudaFuncSetAttribute(lstm_persistent,
                         cudaFuncAttributeMaxDynamicSharedMemorySize, 53248);

    prep_x<<<(256 * 256 * 64 + 255) / 256, 256>>>(x);
    prep_w0<<<(16 * 576 * 128 + 255) / 256, 256>>>(Wih0, Whh0);
    prep_w1<<<(16 * 1024 * 128 + 255) / 256, 256>>>(Wih1, Whh1);
    prep_bias<<<(4096 + 255) / 256, 256>>>(bih0, bhh0, bih1, bhh1);
    prep_zero<<<(2 * 256 * 512 + 255) / 256, 256>>>();
    lstm_persistent<<<NBLK, THREADS, 53248>>>(Wfc, bfc, out);
}

// round 4
// speedup vs baseline: 1.2869x; 1.2708x over previous
#include <cuda_runtime.h>
#include <cstdint>

#define NBLK 128
#define THREADS 256

// ---------------- device globals (pre-packed padded tile images) -----------
// A-block: 64 rows x 36 floats (cols 32..35 pad) = 9216 B, contiguous.
// B-chunk: 32 k-rows x 132 floats (cols 128..131 pad) = 16896 B, contiguous.
__device__ float g_xA[256 * 4 * 2 * 2304];        // [t][mt][kt2] A-blocks
__device__ float g_hA0[2 * 4 * 16 * 2304];        // [par][mt][strip] A-blocks
__device__ float g_hA1[2 * 4 * 16 * 2304];
__device__ float g_Bp0[16 * 18 * 4224];           // [strip][kt] B-chunks
__device__ float g_Bp1[16 * 32 * 4224];
__device__ float g_bias0[16 * 128];
__device__ float g_bias1[16 * 128];
__device__ float g_h1x[256 * 512];                // exact h1 at t=255 (FC input)
__device__ unsigned g_count;
__device__ unsigned g_phase;

// ---------------- helpers ---------------------------------------------------
__device__ __forceinline__ float tf32r(float x) {
    unsigned u;
    asm("cvt.rna.tf32.f32 %0, %1;" : "=r"(u) : "f"(x));
    return __uint_as_float(u);
}
__device__ __forceinline__ uint32_t smem_u32(const void* p) {
    uint32_t a;
    asm("{ .reg .u64 t; cvta.to.shared.u64 t, %1; cvt.u32.u64 %0, t; }" : "=r"(a) : "l"(p));
    return a;
}
#define MBAR_INIT(a, n) \
    asm volatile("mbarrier.init.shared.b64 [%0], %1;" :: "r"(a), "r"((uint32_t)(n)) : "memory")
#define MBAR_EXPECT_TX(a, b) \
    asm volatile("mbarrier.arrive.expect_tx.shared.b64 _, [%0], %1;" :: "r"(a), "r"((uint32_t)(b)) : "memory")
#define MBAR_WAIT(a, p) do {                                                              \
    asm volatile("{\n\t.reg .pred P1;\n\t"                                                \
        "WL_%=:\n\t"                                                                      \
        "mbarrier.try_wait.parity.acquire.cta.shared::cta.b64 P1, [%0], %1, 0x989680;\n\t"\
        "@P1 bra.uni WD_%=;\n\t"                                                          \
        "bra.uni WL_%=;\n\t"                                                              \
        "WD_%=:\n\t}"                                                                     \
        :: "r"(a), "r"((uint32_t)(p)) : "memory");                                        \
} while (0)
#define BULK_G2S(dst, src, bytes, mbar)                                                   \
    asm volatile("cp.async.bulk.shared::cluster.global.mbarrier::complete_tx::bytes "     \
                 "[%0], [%1], %2, [%3];"                                                  \
        :: "r"(dst), "l"(src), "r"((uint32_t)(bytes)), "r"(mbar) : "memory")

__device__ __forceinline__ void mma8(float* c, const unsigned* a, const unsigned* b) {
    asm volatile(
        "mma.sync.aligned.m16n8k8.row.col.f32.tf32.tf32.f32 "
        "{%0,%1,%2,%3},{%4,%5,%6,%7},{%8,%9},{%0,%1,%2,%3};"
        : "+f"(c[0]), "+f"(c[1]), "+f"(c[2]), "+f"(c[3])
        : "r"(a[0]), "r"(a[1]), "r"(a[2]), "r"(a[3]), "r"(b[0]), "r"(b[1]));
}

// ---------------- prep kernels ----------------------------------------------
__global__ void prep_x(const float* __restrict__ x) {
    int idx = blockIdx.x * blockDim.x + threadIdx.x;
    if (idx >= 256 * 4 * 2 * 64 * 32) return;
    int c   = idx & 31;
    int r   = (idx >> 5) & 63;
    int kt2 = (idx >> 11) & 1;
    int mt  = (idx >> 12) & 3;
    int t   = idx >> 14;
    int b = mt * 64 + r, d = kt2 * 32 + c;
    g_xA[(((t * 4 + mt) * 2 + kt2) * 2304) + r * 36 + c] = tf32r(x[(b * 256 + t) * 64 + d]);
}
__global__ void prep_w0(const float* __restrict__ Wih, const float* __restrict__ Whh) {
    int idx = blockIdx.x * blockDim.x + threadIdx.x;
    if (idx >= 16 * 18 * 32 * 128) return;
    int c  = idx & 127;
    int kr = (idx >> 7) & 31;
    int kt = (idx >> 12) % 18;
    int st = idx / (4096 * 18);
    int g = c & 3, hl = c >> 2;
    int row = g * 512 + st * 32 + hl;
    int k = kt * 32 + kr;
    float v = (k < 64) ? Wih[row * 64 + k] : Whh[row * 512 + (k - 64)];
    g_Bp0[(st * 18 + kt) * 4224 + kr * 132 + c] = tf32r(v);
}
__global__ void prep_w1(const float* __restrict__ Wih, const float* __restrict__ Whh) {
    int idx = blockIdx.x * blockDim.x + threadIdx.x;
    if (idx >= 16 * 32 * 32 * 128) return;
    int c  = idx & 127;
    int kr = (idx >> 7) & 31;
    int kt = (idx >> 12) & 31;
    int st = idx >> 17;
    int g = c & 3, hl = c >> 2;
    int row = g * 512 + st * 32 + hl;
    int k = kt * 32 + kr;
    float v = (k < 512) ? Wih[row * 512 + k] : Whh[row * 512 + (k - 512)];
    g_Bp1[(st * 32 + kt) * 4224 + kr * 132 + c] = tf32r(v);
}
__global__ void prep_bias(const float* __restrict__ bi0, const float* __restrict__ bh0,
                          const float* __restrict__ bi1, const float* __restrict__ bh1) {
    int idx = blockIdx.x * blockDim.x + threadIdx.x;
    if (idx >= 2 * 2048) return;
    int l = idx >> 11;
    int rr = idx & 2047;
    int c = rr & 127, st = rr >> 7;
    int g = c & 3, hl = c >> 2;
    int row = g * 512 + st * 32 + hl;
    float v = l ? (bi1[row] + bh1[row]) : (bi0[row] + bh0[row]);
    (l ? g_bias1 : g_bias0)[rr] = v;
}
__global__ void prep_zero() {
    int idx = blockIdx.x * blockDim.x + threadIdx.x;
    if (idx < 2 * 4 * 16 * 2304) { g_hA0[idx] = 0.f; g_hA1[idx] = 0.f; }
    if (idx == 0) { g_count = 0u; g_phase = 0u; }
}

// ---------------- tile issue (one thread) ------------------------------------
__device__ __forceinline__ void issue_tiles(int layer, int s, int mt, int rp, int strip,
                                            int kt, uint32_t aS, uint32_t bS, uint32_t bar) {
    const float* asrc;
    if (layer == 0) {
        asrc = (kt < 2) ? &g_xA[((s * 4 + mt) * 2 + kt) * 2304]
                        : &g_hA0[((rp * 4 + mt) * 16 + (kt - 2)) * 2304];
    } else {
        asrc = (kt < 16) ? &g_hA0[((rp * 4 + mt) * 16 + kt) * 2304]
                         : &g_hA1[((rp * 4 + mt) * 16 + (kt - 16)) * 2304];
    }
    const float* bsrc = layer ? &g_Bp1[(strip * 32 + kt) * 4224]
                              : &g_Bp0[(strip * 18 + kt) * 4224];
    MBAR_EXPECT_TX(bar, 9216 + 16896);
    BULK_G2S(aS, asrc, 9216, bar);
    BULK_G2S(bS, bsrc, 16896, bar);
}

// ---------------- persistent LSTM kernel ------------------------------------
__global__ __launch_bounds__(THREADS, 1)
void lstm_persistent(const float* __restrict__ Wfc, const float* __restrict__ bfc,
                     float* __restrict__ out) {
    extern __shared__ float dsm[];
    float* As[2] = { dsm, dsm + 2304 };            // 64 x 36
    float* Bs[2] = { dsm + 4608, dsm + 8832 };     // 32 x 132
    __shared__ __align__(8) unsigned long long mbar[2];
    __shared__ float bias_s[128];

    const int tid   = threadIdx.x;
    const int lane  = tid & 31;
    const int warp  = tid >> 5;
    const int warpM = warp >> 2;
    const int warpN = warp & 3;
    const int bid   = blockIdx.x;
    const int layer = bid >> 6;
    const int tile  = bid & 63;
    const int mt    = tile & 3;
    const int m0    = mt * 64;
    const int strip = tile >> 2;
    const int ktiles = layer ? 32 : 18;
    const float* biasg = (layer ? g_bias1 : g_bias0) + strip * 128;

    uint32_t aS[2] = { smem_u32(As[0]), smem_u32(As[1]) };
    uint32_t bS[2] = { smem_u32(Bs[0]), smem_u32(Bs[1]) };
    uint32_t bar[2] = { smem_u32(&mbar[0]), smem_u32(&mbar[1]) };

    if (tid == 0) { MBAR_INIT(bar[0], 1); MBAR_INIT(bar[1], 1); }
    for (int i = tid; i < 128; i += THREADS) bias_s[i] = biasg[i];
    __syncthreads();

    float cst[8];
#pragma unroll
    for (int j = 0; j < 8; j++) cst[j] = 0.f;
    int ph[2] = { 0, 0 };
    unsigned target = 0;

    for (int s = 0; s <= 256; s++) {
        bool active = layer ? (s >= 1) : (s < 256);
        if (active) {
            const int rp = (s + 1) & 1;
            float acc[2][4][4];
#pragma unroll
            for (int mi = 0; mi < 2; mi++)
#pragma unroll
                for (int ni = 0; ni < 4; ni++)
#pragma unroll
                    for (int q = 0; q < 4; q++) acc[mi][ni][q] = 0.f;

            if (tid == 0) issue_tiles(layer, s, mt, rp, strip, 0, aS[0], bS[0], bar[0]);

            for (int kt = 0; kt < ktiles; kt++) {
                int b = kt & 1;
                if (kt + 1 < ktiles && tid == 0)
                    issue_tiles(layer, s, mt, rp, strip, kt + 1,
                                aS[(kt + 1) & 1], bS[(kt + 1) & 1], bar[(kt + 1) & 1]);
                MBAR_WAIT(bar[b], ph[b]);
                ph[b] ^= 1;

                const float* as = As[b];
                const float* bs = Bs[b];
#pragma unroll
                for (int kk = 0; kk < 4; kk++) {
                    unsigned afr[2][4], bfr[4][2];
#pragma unroll
                    for (int mi = 0; mi < 2; mi++) {
                        int rb = warpM * 32 + mi * 16 + (lane >> 2);
                        int cb = kk * 8 + (lane & 3);
                        afr[mi][0] = __float_as_uint(as[rb * 36 + cb]);
                        afr[mi][1] = __float_as_uint(as[(rb + 8) * 36 + cb]);
                        afr[mi][2] = __float_as_uint(as[rb * 36 + cb + 4]);
                        afr[mi][3] = __float_as_uint(as[(rb + 8) * 36 + cb + 4]);
                    }
#pragma unroll
                    for (int ni = 0; ni < 4; ni++) {
                        int nb = warpN * 32 + ni * 8 + (lane >> 2);
                        int kb = kk * 8 + (lane & 3);
                        bfr[ni][0] = __float_as_uint(bs[kb * 132 + nb]);
                        bfr[ni][1] = __float_as_uint(bs[(kb + 4) * 132 + nb]);
                    }
#pragma unroll
                    for (int mi = 0; mi < 2; mi++)
#pragma unroll
                        for (int ni = 0; ni < 4; ni++)
                            mma8(acc[mi][ni], afr[mi], bfr[ni]);
                }
                __syncthreads();   // stage reuse fence
            }

            // gates -> smem, then pointwise LSTM cell
            float* Gs = dsm;   // [64][132]
#pragma unroll
            for (int mi = 0; mi < 2; mi++) {
                int rr = warpM * 32 + mi * 16 + (lane >> 2);
#pragma unroll
                for (int ni = 0; ni < 4; ni++) {
                    int cc = warpN * 32 + ni * 8 + (lane & 3) * 2;
                    Gs[rr * 132 + cc]           = acc[mi][ni][0];
                    Gs[rr * 132 + cc + 1]       = acc[mi][ni][1];
                    Gs[(rr + 8) * 132 + cc]     = acc[mi][ni][2];
                    Gs[(rr + 8) * 132 + cc + 1] = acc[mi][ni][3];
                }
            }
            __syncthreads();

            int r   = tid >> 2;
            int hl0 = (tid & 3) * 8;
            float* hout = (layer ? g_hA1 : g_hA0)
                          + (((s & 1) * 4 + mt) * 16 + strip) * 2304;
#pragma unroll
            for (int j = 0; j < 8; j++) {
                int c4 = (hl0 + j) * 4;
                float ip = Gs[r * 132 + c4 + 0] + bias_s[c4 + 0];
                float fp = Gs[r * 132 + c4 + 1] + bias_s[c4 + 1];
                float gp = Gs[r * 132 + c4 + 2] + bias_s[c4 + 2];
                float op = Gs[r * 132 + c4 + 3] + bias_s[c4 + 3];
                float ig = 1.f / (1.f + __expf(-ip));
                float fg = 1.f / (1.f + __expf(-fp));
                float gg = tanhf(gp);
                float og = 1.f / (1.f + __expf(-op));
                float cn = fg * cst[j] + ig * gg;
                cst[j] = cn;
                float h = og * tanhf(cn);
                hout[r * 36 + hl0 + j] = tf32r(h);
                if (layer && s == 256)
                    g_h1x[(m0 + r) * 512 + strip * 32 + hl0 + j] = h;
            }
        }

        // ---- grid barrier ----
        target++;
        __threadfence();
        __syncthreads();
        if (tid == 0) {
            unsigned arrived = atomicAdd(&g_count, 1u) + 1u;
            if ((arrived & (NBLK - 1)) == 0u) {
                atomicAdd(&g_phase, 1u);
            } else {
                while (*((volatile unsigned*)&g_phase) < target) { }
            }
            __threadfence();
        }
        __syncthreads();
    }

    // ---- final FC ----
    float* red = dsm;
    for (int r2 = 0; r2 < 2; r2++) {
        int b = bid * 2 + r2;
        float p = 0.f;
        for (int k = tid; k < 512; k += THREADS)
            p += __ldcg(&g_h1x[b * 512 + k]) * __ldg(&Wfc[k]);
        red[tid] = p;
        __syncthreads();
        for (int off = 128; off > 0; off >>= 1) {
            if (tid < off) red[tid] += red[tid + off];
            __syncthreads();
        }
        if (tid == 0) out[b] = red[0] + __ldg(bfc);
        __syncthreads();
    }
}

// ---------------- launch -----------------------------------------------------
extern "C" void kernel_launch(void* const* d_in, const int* in_sizes, int n_in,
                              void* d_out, int out_size) {
    const float* x    = (const float*)d_in[0];
    const float* Wih0 = (const float*)d_in[1];
    const float* Whh0 = (const float*)d_in[2];
    const float* bih0 = (const float*)d_in[3];
    const float* bhh0 = (const float*)d_in[4];
    const float* Wih1 = (const float*)d_in[5];
    const float* Whh1 = (const float*)d_in[6];
    const float* bih1 = (const float*)d_in[7];
    const float* bhh1 = (const float*)d_in[8];
    const float* Wfc  = (const float*)d_in[9];
    const float* bfc  = (const float*)d_in[10];
    float* out = (float*)d_out;

    cudaFuncSetAttribute(lstm_persistent,
                         cudaFuncAttributeMaxDynamicSharedMemorySize, 53248);

    prep_x<<<(256 * 4 * 2 * 64 * 32 + 255) / 256, 256>>>(x);
    prep_w0<<<(16 * 18 * 32 * 128 + 255) / 256, 256>>>(Wih0, Whh0);
    prep_w1<<<(16 * 32 * 32 * 128 + 255) / 256, 256>>>(Wih1, Whh1);
    prep_bias<<<(4096 + 255) / 256, 256>>>(bih0, bhh0, bih1, bhh1);
    prep_zero<<<(2 * 4 * 16 * 2304 + 255) / 256, 256>>>();
    lstm_persistent<<<NBLK, THREADS, 53248>>>(Wfc, bfc, out);
}

// round 6
// speedup vs baseline: 1.8532x; 1.4401x over previous
#include <cuda_runtime.h>
#include <cuda_fp16.h>
#include <cstdint>

#define NBLK    128
#define THREADS 256
#define STAGES  6
#define STAGE_BYTES 13824       // A 4608B + B 9216B

// ---------------- device globals: fp16 pre-packed tile images --------------
// A-block: 64 rows x 36 halves (32 k + 4 pad) = 4608 B
// B-block: 128 n-rows x 36 halves = 9216 B
__device__ __half g_xA[256 * 4 * 2 * 2304];     // [t][mt][kc]
__device__ __half g_hA0[2 * 4 * 16 * 2304];     // [par][mt][strip]
__device__ __half g_hA1[2 * 4 * 16 * 2304];
__device__ __half g_Bp0[16 * 18 * 4608];        // [strip][kt]
__device__ __half g_Bp1[16 * 32 * 4608];
__device__ float g_bias0[16 * 128];
__device__ float g_bias1[16 * 128];
__device__ float g_h1x[256 * 512];
__device__ unsigned g_count, g_phase;

// ---------------- helpers ----------------------------------------------------
__device__ __forceinline__ uint32_t smem_u32(const void* p) {
    uint32_t a;
    asm("{ .reg .u64 t; cvta.to.shared.u64 t, %1; cvt.u32.u64 %0, t; }" : "=r"(a) : "l"(p));
    return a;
}
#define MBAR_INIT(a, n) \
    asm volatile("mbarrier.init.shared.b64 [%0], %1;" :: "r"(a), "r"((uint32_t)(n)) : "memory")
#define MBAR_EXPECT_TX(a, b) \
    asm volatile("mbarrier.arrive.expect_tx.shared.b64 _, [%0], %1;" :: "r"(a), "r"((uint32_t)(b)) : "memory")
#define MBAR_ARRIVE(a) \
    asm volatile("mbarrier.arrive.shared.b64 _, [%0];" :: "r"(a) : "memory")
#define MBAR_WAIT(a, p) do {                                                               \
    asm volatile("{\n\t.reg .pred P1;\n\t"                                                 \
        "WL_%=:\n\t"                                                                       \
        "mbarrier.try_wait.parity.acquire.cta.shared::cta.b64 P1, [%0], %1, 0x989680;\n\t" \
        "@P1 bra.uni WD_%=;\n\t"                                                           \
        "bra.uni WL_%=;\n\t"                                                               \
        "WD_%=:\n\t}"                                                                      \
        :: "r"(a), "r"((uint32_t)(p)) : "memory");                                         \
} while (0)
#define BULK_G2S(dst, src, bytes, mbar)                                                    \
    asm volatile("cp.async.bulk.shared::cluster.global.mbarrier::complete_tx::bytes "      \
                 "[%0], [%1], %2, [%3];"                                                   \
        :: "r"(dst), "l"(src), "r"((uint32_t)(bytes)), "r"(mbar) : "memory")

__device__ __forceinline__ void mma16(float* c, const uint32_t* a, const uint32_t* b) {
    asm volatile(
        "mma.sync.aligned.m16n8k16.row.col.f32.f16.f16.f32 "
        "{%0,%1,%2,%3},{%4,%5,%6,%7},{%8,%9},{%0,%1,%2,%3};"
        : "+f"(c[0]), "+f"(c[1]), "+f"(c[2]), "+f"(c[3])
        : "r"(a[0]), "r"(a[1]), "r"(a[2]), "r"(a[3]), "r"(b[0]), "r"(b[1]));
}
__device__ __forceinline__ float fsig(float x) { return 1.f / (1.f + __expf(-x)); }

// ---------------- prep kernels -------------------------------------------------
__global__ void prep_x(const float* __restrict__ x) {
    int idx = blockIdx.x * blockDim.x + threadIdx.x;
    if (idx >= 256 * 4 * 2 * 64 * 32) return;
    int kk = idx & 31;
    int r  = (idx >> 5) & 63;
    int kc = (idx >> 11) & 1;
    int mt = (idx >> 12) & 3;
    int t  = idx >> 14;
    int b = mt * 64 + r, d = kc * 32 + kk;
    g_xA[((t * 4 + mt) * 2 + kc) * 2304 + r * 36 + kk] = __float2half(x[(b * 256 + t) * 64 + d]);
}
__global__ void prep_w0(const float* __restrict__ Wih, const float* __restrict__ Whh) {
    int idx = blockIdx.x * blockDim.x + threadIdx.x;
    if (idx >= 16 * 18 * 128 * 32) return;
    int kk = idx & 31;
    int n  = (idx >> 5) & 127;
    int kt = (idx >> 12) % 18;
    int nt = idx / (18 * 4096);
    int row = (n & 3) * 512 + nt * 32 + (n >> 2);
    int k = kt * 32 + kk;
    float v = (k < 64) ? Wih[row * 64 + k] : Whh[row * 512 + (k - 64)];
    g_Bp0[(nt * 18 + kt) * 4608 + n * 36 + kk] = __float2half(v);
}
__global__ void prep_w1(const float* __restrict__ Wih, const float* __restrict__ Whh) {
    int idx = blockIdx.x * blockDim.x + threadIdx.x;
    if (idx >= 16 * 32 * 128 * 32) return;
    int kk = idx & 31;
    int n  = (idx >> 5) & 127;
    int kt = (idx >> 12) & 31;
    int nt = idx >> 17;
    int row = (n & 3) * 512 + nt * 32 + (n >> 2);
    int k = kt * 32 + kk;
    float v = (k < 512) ? Wih[row * 512 + k] : Whh[row * 512 + (k - 512)];
    g_Bp1[(nt * 32 + kt) * 4608 + n * 36 + kk] = __float2half(v);
}
__global__ void prep_bias(const float* __restrict__ bi0, const float* __restrict__ bh0,
                          const float* __restrict__ bi1, const float* __restrict__ bh1) {
    int idx = blockIdx.x * blockDim.x + threadIdx.x;
    if (idx >= 2 * 2048) return;
    int l = idx >> 11;
    int rr = idx & 2047;
    int c = rr & 127, nt = rr >> 7;
    int row = (c & 3) * 512 + nt * 32 + (c >> 2);
    float v = l ? (bi1[row] + bh1[row]) : (bi0[row] + bh0[row]);
    (l ? g_bias1 : g_bias0)[rr] = v;
}
__global__ void prep_zero() {
    int idx = blockIdx.x * blockDim.x + threadIdx.x;
    if (idx < 2 * 4 * 16 * 2304) {
        g_hA0[idx] = __float2half(0.f);
        g_hA1[idx] = __float2half(0.f);
    }
    if (idx == 0) { g_count = 0u; g_phase = 0u; }
}

// ---------------- persistent LSTM kernel ---------------------------------------
__global__ __launch_bounds__(THREADS, 1)
void lstm_persistent(const float* __restrict__ Wfc, const float* __restrict__ bfc,
                     float* __restrict__ out) {
    extern __shared__ char dsm_raw[];
    __shared__ __align__(8) unsigned long long mb_full[STAGES], mb_empty[STAGES];
    __shared__ float Gs[64 * 132];
    __shared__ float bias_s[128];
    __shared__ float red[THREADS];

    const int tid   = threadIdx.x;
    const int lane  = tid & 31;
    const int warp  = tid >> 5;
    const int warpM = warp >> 2;
    const int warpN = warp & 3;
    const int bid   = blockIdx.x;
    const int layer = bid >> 6;
    const int tile  = bid & 63;
    const int mt    = tile & 3;
    const int m0    = mt * 64;
    const int strip = tile >> 2;
    const int CH    = layer ? 32 : 18;

    uint32_t rawu  = smem_u32(dsm_raw);
    uint32_t dsm_u = (rawu + 127u) & ~127u;
    char* sbase = dsm_raw + (dsm_u - rawu);
    uint32_t fullA[STAGES], emptyA[STAGES], aS[STAGES], bS[STAGES];
#pragma unroll
    for (int s = 0; s < STAGES; s++) {
        aS[s] = dsm_u + s * STAGE_BYTES;
        bS[s] = aS[s] + 4608;
        fullA[s]  = smem_u32(&mb_full[s]);
        emptyA[s] = smem_u32(&mb_empty[s]);
    }
    if (tid == 0) {
#pragma unroll
        for (int s = 0; s < STAGES; s++) { MBAR_INIT(fullA[s], 1); MBAR_INIT(emptyA[s], 8); }
    }
    for (int i = tid; i < 128; i += THREADS)
        bias_s[i] = ((layer ? g_bias1 : g_bias0) + strip * 128)[i];
    __syncthreads();

    float cst[8];
#pragma unroll
    for (int j = 0; j < 8; j++) cst[j] = 0.f;

    int p_st = 0, p_ph = 1;   // producer (tid 0): empty-waits start passing
    int c_st = 0, c_ph = 0;   // consumer (all threads)
    unsigned target = 0;

    for (int s = 0; s <= 256; s++) {
        bool active = layer ? (s >= 1) : (s < 256);
        if (active) {
            const int rp = (s + 1) & 1;

            // producer issue lambda (tid 0 only)
            auto issue = [&](int kt) {
                const __half* asrc;
                if (layer == 0)
                    asrc = (kt < 2) ? &g_xA[((s * 4 + mt) * 2 + kt) * 2304]
                                    : &g_hA0[((rp * 4 + mt) * 16 + (kt - 2)) * 2304];
                else
                    asrc = (kt < 16) ? &g_hA0[((rp * 4 + mt) * 16 + kt) * 2304]
                                     : &g_hA1[((rp * 4 + mt) * 16 + (kt - 16)) * 2304];
                const __half* bsrc = layer ? &g_Bp1[(strip * 32 + kt) * 4608]
                                           : &g_Bp0[(strip * 18 + kt) * 4608];
                MBAR_WAIT(emptyA[p_st], p_ph);
                MBAR_EXPECT_TX(fullA[p_st], STAGE_BYTES);
                BULK_G2S(aS[p_st], asrc, 4608, fullA[p_st]);
                BULK_G2S(bS[p_st], bsrc, 9216, fullA[p_st]);
                if (++p_st == STAGES) { p_st = 0; p_ph ^= 1; }
            };

            if (tid == 0)
                for (int i = 0; i < STAGES; i++) issue(i);

            float acc[2][4][4];
#pragma unroll
            for (int mi = 0; mi < 2; mi++)
#pragma unroll
                for (int ni = 0; ni < 4; ni++)
#pragma unroll
                    for (int q = 0; q < 4; q++) acc[mi][ni][q] = 0.f;

            for (int kt = 0; kt < CH; kt++) {
                int st = c_st;
                MBAR_WAIT(fullA[st], c_ph);
                if (++c_st == STAGES) { c_st = 0; c_ph ^= 1; }

                const uint32_t* aw = (const uint32_t*)(sbase + st * STAGE_BYTES);
                const uint32_t* bw = (const uint32_t*)(sbase + st * STAGE_BYTES + 4608);
#pragma unroll
                for (int kk = 0; kk < 2; kk++) {
                    uint32_t af[2][4], bf[4][2];
#pragma unroll
                    for (int mi = 0; mi < 2; mi++) {
                        int rb = warpM * 32 + mi * 16 + (lane >> 2);
                        int wi = rb * 18 + (lane & 3) + kk * 8;
                        af[mi][0] = aw[wi];
                        af[mi][1] = aw[wi + 8 * 18];
                        af[mi][2] = aw[wi + 4];
                        af[mi][3] = aw[wi + 8 * 18 + 4];
                    }
#pragma unroll
                    for (int ni = 0; ni < 4; ni++) {
                        int nb = warpN * 32 + ni * 8 + (lane >> 2);
                        int wi = nb * 18 + (lane & 3) + kk * 8;
                        bf[ni][0] = bw[wi];
                        bf[ni][1] = bw[wi + 4];
                    }
#pragma unroll
                    for (int mi = 0; mi < 2; mi++)
#pragma unroll
                        for (int ni = 0; ni < 4; ni++)
                            mma16(acc[mi][ni], af[mi], bf[ni]);
                }
                if (lane == 0) MBAR_ARRIVE(emptyA[st]);
                if (tid == 0 && kt + STAGES < CH) issue(kt + STAGES);
            }

            // accumulators -> Gs -> LSTM pointwise
#pragma unroll
            for (int mi = 0; mi < 2; mi++) {
                int rr = warpM * 32 + mi * 16 + (lane >> 2);
#pragma unroll
                for (int ni = 0; ni < 4; ni++) {
                    int cc = warpN * 32 + ni * 8 + (lane & 3) * 2;
                    Gs[rr * 132 + cc]           = acc[mi][ni][0];
                    Gs[rr * 132 + cc + 1]       = acc[mi][ni][1];
                    Gs[(rr + 8) * 132 + cc]     = acc[mi][ni][2];
                    Gs[(rr + 8) * 132 + cc + 1] = acc[mi][ni][3];
                }
            }
            __syncthreads();

            int r   = tid >> 2;
            int hl0 = (tid & 3) * 8;
            __half* hout = (layer ? g_hA1 : g_hA0)
                           + (((s & 1) * 4 + mt) * 16 + strip) * 2304;
#pragma unroll
            for (int j = 0; j < 8; j++) {
                int c4 = (hl0 + j) * 4;
                float ip = Gs[r * 132 + c4 + 0] + bias_s[c4 + 0];
                float fp = Gs[r * 132 + c4 + 1] + bias_s[c4 + 1];
                float gp = Gs[r * 132 + c4 + 2] + bias_s[c4 + 2];
                float op = Gs[r * 132 + c4 + 3] + bias_s[c4 + 3];
                float cn = fsig(fp) * cst[j] + fsig(ip) * tanhf(gp);
                cst[j] = cn;
                float h = fsig(op) * tanhf(cn);
                hout[r * 36 + hl0 + j] = __float2half(h);
                if (layer && s == 256)
                    g_h1x[(m0 + r) * 512 + strip * 32 + hl0 + j] = h;
            }
        }

        // -------- grid barrier --------
        target++;
        __threadfence();
        __syncthreads();
        if (tid == 0) {
            unsigned arrived = atomicAdd(&g_count, 1u) + 1u;
            if ((arrived & (NBLK - 1)) == 0u) {
                atomicAdd(&g_phase, 1u);
            } else {
                while (*((volatile unsigned*)&g_phase) < target) { }
            }
            __threadfence();
        }
        __syncthreads();
    }

    // -------- final FC --------
    for (int r2 = 0; r2 < 2; r2++) {
        int b = bid * 2 + r2;
        float p = 0.f;
        for (int k = tid; k < 512; k += THREADS)
            p += __ldcg(&g_h1x[b * 512 + k]) * __ldg(&Wfc[k]);
        red[tid] = p;
        __syncthreads();
        for (int off = 128; off > 0; off >>= 1) {
            if (tid < off) red[tid] += red[tid + off];
            __syncthreads();
        }
        if (tid == 0) out[b] = red[0] + __ldg(bfc);
        __syncthreads();
    }
}

// ---------------- launch --------------------------------------------------------
extern "C" void kernel_launch(void* const* d_in, const int* in_sizes, int n_in,
                              void* d_out, int out_size) {
    const float* x    = (const float*)d_in[0];
    const float* Wih0 = (const float*)d_in[1];
    const float* Whh0 = (const float*)d_in[2];
    const float* bih0 = (const float*)d_in[3];
    const float* bhh0 = (const float*)d_in[4];
    const float* Wih1 = (const float*)d_in[5];
    const float* Whh1 = (const float*)d_in[6];
    const float* bih1 = (const float*)d_in[7];
    const float* bhh1 = (const float*)d_in[8];
    const float* Wfc  = (const float*)d_in[9];
    const float* bfc  = (const float*)d_in[10];
    float* out = (float*)d_out;

    cudaFuncSetAttribute(lstm_persistent,
                         cudaFuncAttributeMaxDynamicSharedMemorySize,
                         STAGES * STAGE_BYTES + 256);

    prep_x<<<(256 * 4 * 2 * 64 * 32 + 255) / 256, 256>>>(x);
    prep_w0<<<(16 * 18 * 128 * 32 + 255) / 256, 256>>>(Wih0, Whh0);
    prep_w1<<<(16 * 32 * 128 * 32 + 255) / 256, 256>>>(Wih1, Whh1);
    prep_bias<<<(4096 + 255) / 256, 256>>>(bih0, bhh0, bih1, bhh1);
    prep_zero<<<(2 * 4 * 16 * 2304 + 255) / 256, 256>>>();
    lstm_persistent<<<NBLK, THREADS, STAGES * STAGE_BYTES + 256>>>(Wfc, bfc, out);
}

// round 7
// speedup vs baseline: 2.3507x; 1.2685x over previous
#include <cuda_runtime.h>
#include <cuda_fp16.h>
#include <cstdint>

#define NBLK    128
#define THREADS 256
#define STAGES  4
#define A_BYTES 9216          // 64 rows x 72 halves (2 K32 sub-blocks of 64x36)
#define B_BYTES 18432         // 2 K32 sub-blocks of 128x36 halves
#define STAGE_BYTES (A_BYTES + B_BYTES)   // 27648

// ---------------- device globals: fp16 pre-packed tile images --------------
// A K32 block: 64 rows x 36 halves = 4608 B; B K32 block: 128 rows x 36 halves = 9216 B
__device__ __half g_xA[256 * 4 * 2 * 2304];     // [t][mt][kc]
__device__ __half g_hA0[2 * 4 * 16 * 2304];     // [par][mt][strip]
__device__ __half g_hA1[2 * 4 * 16 * 2304];
__device__ __half g_Bp0[16 * 18 * 4608];        // [strip][kt32]
__device__ __half g_Bp1[16 * 32 * 4608];
__device__ float g_bias0[16 * 128];
__device__ float g_bias1[16 * 128];
__device__ float g_part[64 * 64 * 128];         // per-tile fp32 gate partials
__device__ unsigned g_pflag[64];
__device__ float g_h1x[256 * 512];
__device__ unsigned g_count, g_phase;

// ---------------- helpers ----------------------------------------------------
__device__ __forceinline__ uint32_t smem_u32(const void* p) {
    uint32_t a;
    asm("{ .reg .u64 t; cvta.to.shared.u64 t, %1; cvt.u32.u64 %0, t; }" : "=r"(a) : "l"(p));
    return a;
}
#define MBAR_INIT(a, n) \
    asm volatile("mbarrier.init.shared.b64 [%0], %1;" :: "r"(a), "r"((uint32_t)(n)) : "memory")
#define MBAR_EXPECT_TX(a, b) \
    asm volatile("mbarrier.arrive.expect_tx.shared.b64 _, [%0], %1;" :: "r"(a), "r"((uint32_t)(b)) : "memory")
#define MBAR_ARRIVE(a) \
    asm volatile("mbarrier.arrive.shared.b64 _, [%0];" :: "r"(a) : "memory")
#define MBAR_WAIT(a, p) do {                                                               \
    asm volatile("{\n\t.reg .pred P1;\n\t"                                                 \
        "WL_%=:\n\t"                                                                       \
        "mbarrier.try_wait.parity.acquire.cta.shared::cta.b64 P1, [%0], %1, 0x989680;\n\t" \
        "@P1 bra.uni WD_%=;\n\t"                                                           \
        "bra.uni WL_%=;\n\t"                                                               \
        "WD_%=:\n\t}"                                                                      \
        :: "r"(a), "r"((uint32_t)(p)) : "memory");                                         \
} while (0)
#define BULK_G2S(dst, src, bytes, mbar)                                                    \
    asm volatile("cp.async.bulk.shared::cluster.global.mbarrier::complete_tx::bytes "      \
                 "[%0], [%1], %2, [%3];"                                                   \
        :: "r"(dst), "l"(src), "r"((uint32_t)(bytes)), "r"(mbar) : "memory")

__device__ __forceinline__ void mma16(float* c, const uint32_t* a, const uint32_t* b) {
    asm volatile(
        "mma.sync.aligned.m16n8k16.row.col.f32.f16.f16.f32 "
        "{%0,%1,%2,%3},{%4,%5,%6,%7},{%8,%9},{%0,%1,%2,%3};"
        : "+f"(c[0]), "+f"(c[1]), "+f"(c[2]), "+f"(c[3])
        : "r"(a[0]), "r"(a[1]), "r"(a[2]), "r"(a[3]), "r"(b[0]), "r"(b[1]));
}
__device__ __forceinline__ float fsig(float x) { return 1.f / (1.f + __expf(-x)); }
__device__ __forceinline__ float ftanh(float x) { return 1.f - 2.f / (__expf(2.f * x) + 1.f); }

// ---------------- prep kernels -------------------------------------------------
__global__ void prep_x(const float* __restrict__ x) {
    int idx = blockIdx.x * blockDim.x + threadIdx.x;
    if (idx >= 256 * 4 * 2 * 64 * 32) return;
    int kk = idx & 31;
    int r  = (idx >> 5) & 63;
    int kc = (idx >> 11) & 1;
    int mt = (idx >> 12) & 3;
    int t  = idx >> 14;
    int b = mt * 64 + r, d = kc * 32 + kk;
    g_xA[((t * 4 + mt) * 2 + kc) * 2304 + r * 36 + kk] = __float2half(x[(b * 256 + t) * 64 + d]);
}
__global__ void prep_w0(const float* __restrict__ Wih, const float* __restrict__ Whh) {
    int idx = blockIdx.x * blockDim.x + threadIdx.x;
    if (idx >= 16 * 18 * 128 * 32) return;
    int kk = idx & 31;
    int n  = (idx >> 5) & 127;
    int kt = (idx >> 12) % 18;
    int nt = idx / (18 * 4096);
    int row = (n & 3) * 512 + nt * 32 + (n >> 2);
    int k = kt * 32 + kk;
    float v = (k < 64) ? Wih[row * 64 + k] : Whh[row * 512 + (k - 64)];
    g_Bp0[(nt * 18 + kt) * 4608 + n * 36 + kk] = __float2half(v);
}
__global__ void prep_w1(const float* __restrict__ Wih, const float* __restrict__ Whh) {
    int idx = blockIdx.x * blockDim.x + threadIdx.x;
    if (idx >= 16 * 32 * 128 * 32) return;
    int kk = idx & 31;
    int n  = (idx >> 5) & 127;
    int kt = (idx >> 12) & 31;
    int nt = idx >> 17;
    int row = (n & 3) * 512 + nt * 32 + (n >> 2);
    int k = kt * 32 + kk;
    float v = (k < 512) ? Wih[row * 512 + k] : Whh[row * 512 + (k - 512)];
    g_Bp1[(nt * 32 + kt) * 4608 + n * 36 + kk] = __float2half(v);
}
__global__ void prep_bias(const float* __restrict__ bi0, const float* __restrict__ bh0,
                          const float* __restrict__ bi1, const float* __restrict__ bh1) {
    int idx = blockIdx.x * blockDim.x + threadIdx.x;
    if (idx >= 2 * 2048) return;
    int l = idx >> 11;
    int rr = idx & 2047;
    int c = rr & 127, nt = rr >> 7;
    int row = (c & 3) * 512 + nt * 32 + (c >> 2);
    float v = l ? (bi1[row] + bh1[row]) : (bi0[row] + bh0[row]);
    (l ? g_bias1 : g_bias0)[rr] = v;
}
__global__ void prep_zero() {
    int idx = blockIdx.x * blockDim.x + threadIdx.x;
    if (idx < 2 * 4 * 16 * 2304) {
        g_hA0[idx] = __float2half(0.f);
        g_hA1[idx] = __float2half(0.f);
    }
    if (idx < 64) g_pflag[idx] = 0u;
    if (idx == 0) { g_count = 0u; g_phase = 0u; }
}

// ---------------- persistent LSTM kernel ---------------------------------------
__global__ __launch_bounds__(THREADS, 1)
void lstm_persistent(const float* __restrict__ Wfc, const float* __restrict__ bfc,
                     float* __restrict__ out) {
    extern __shared__ char dsm_raw[];
    __shared__ __align__(8) unsigned long long mb_full[STAGES], mb_empty[STAGES];
    __shared__ float Gs[64 * 132];
    __shared__ float bias_s[128];
    __shared__ float red[THREADS];

    const int tid   = threadIdx.x;
    const int lane  = tid & 31;
    const int warp  = tid >> 5;
    const int warpM = warp >> 2;
    const int warpN = warp & 3;
    const int bid   = blockIdx.x;
    const int layer = bid >> 6;
    const int tile  = bid & 63;
    const int mt    = tile & 3;
    const int m0    = mt * 64;
    const int strip = tile >> 2;

    uint32_t rawu  = smem_u32(dsm_raw);
    uint32_t dsm_u = (rawu + 127u) & ~127u;
    char* sbase = dsm_raw + (dsm_u - rawu);
    uint32_t fullA[STAGES], emptyA[STAGES], aS[STAGES];
#pragma unroll
    for (int s = 0; s < STAGES; s++) {
        aS[s] = dsm_u + s * STAGE_BYTES;
        fullA[s]  = smem_u32(&mb_full[s]);
        emptyA[s] = smem_u32(&mb_empty[s]);
    }
    if (tid == 0) {
#pragma unroll
        for (int s = 0; s < STAGES; s++) { MBAR_INIT(fullA[s], 1); MBAR_INIT(emptyA[s], 8); }
    }
    for (int i = tid; i < 128; i += THREADS)
        bias_s[i] = ((layer ? g_bias1 : g_bias0) + strip * 128)[i];
    __syncthreads();

    float cst[8];
#pragma unroll
    for (int j = 0; j < 8; j++) cst[j] = 0.f;
    float acc[2][4][4];

    int p_st = 0, p_ph = 1;   // producer cursor (tid 0)
    int c_st = 0, c_ph = 0;   // consumer cursor (all threads)
    unsigned target = 0;

    // phase: 0 = layer1-partial computed by layer0 CTA, 1 = own/main chunks
    auto issue = [&](int phase, int c, int s, int rp) {
        const __half* a;
        const __half* b;
        if (layer == 0) {
            if (phase == 0) {
                a = &g_hA1[((rp * 4 + mt) * 16 + 8 + 2 * c) * 2304];
                b = &g_Bp1[(size_t)(strip * 32 + 24 + 2 * c) * 4608];
            } else {
                a = (c == 0) ? &g_xA[(size_t)((s * 4 + mt) * 2) * 2304]
                             : &g_hA0[((rp * 4 + mt) * 16 + (c - 1) * 2) * 2304];
                b = &g_Bp0[(size_t)(strip * 18 + 2 * c) * 4608];
            }
        } else {
            a = (c < 8) ? &g_hA0[((rp * 4 + mt) * 16 + 2 * c) * 2304]
                        : &g_hA1[((rp * 4 + mt) * 16 + (2 * c - 16)) * 2304];
            b = &g_Bp1[(size_t)(strip * 32 + 2 * c) * 4608];
        }
        MBAR_WAIT(emptyA[p_st], p_ph);
        MBAR_EXPECT_TX(fullA[p_st], STAGE_BYTES);
        BULK_G2S(aS[p_st], a, A_BYTES, fullA[p_st]);
        BULK_G2S(aS[p_st] + A_BYTES, b, B_BYTES, fullA[p_st]);
        if (++p_st == STAGES) { p_st = 0; p_ph ^= 1; }
    };

    auto run_gemm = [&](int phase, int nch, int s, int rp, bool hook) {
#pragma unroll
        for (int mi = 0; mi < 2; mi++)
#pragma unroll
            for (int ni = 0; ni < 4; ni++)
#pragma unroll
                for (int q = 0; q < 4; q++) acc[mi][ni][q] = 0.f;
        if (tid == 0) {
            int pre = nch < STAGES ? nch : STAGES;
            for (int i = 0; i < pre; i++) issue(phase, i, s, rp);
        }
        for (int c = 0; c < nch; c++) {
            int st = c_st;
            MBAR_WAIT(fullA[st], c_ph);
            if (++c_st == STAGES) { c_st = 0; c_ph ^= 1; }
            const uint32_t* stW = (const uint32_t*)(sbase + st * STAGE_BYTES);
#pragma unroll
            for (int sub = 0; sub < 2; sub++) {
                const uint32_t* aw = stW + sub * 1152;
                const uint32_t* bw = stW + 2304 + sub * 2304;
#pragma unroll
                for (int kk = 0; kk < 2; kk++) {
                    uint32_t af[2][4], bf[4][2];
#pragma unroll
                    for (int mi = 0; mi < 2; mi++) {
                        int rb = warpM * 32 + mi * 16 + (lane >> 2);
                        int wi = rb * 18 + (lane & 3) + kk * 8;
                        af[mi][0] = aw[wi];
                        af[mi][1] = aw[wi + 8 * 18];
                        af[mi][2] = aw[wi + 4];
                        af[mi][3] = aw[wi + 8 * 18 + 4];
                    }
#pragma unroll
                    for (int ni = 0; ni < 4; ni++) {
                        int nb = warpN * 32 + ni * 8 + (lane >> 2);
                        int wi = nb * 18 + (lane & 3) + kk * 8;
                        bf[ni][0] = bw[wi];
                        bf[ni][1] = bw[wi + 4];
                    }
#pragma unroll
                    for (int mi = 0; mi < 2; mi++)
#pragma unroll
                        for (int ni = 0; ni < 4; ni++)
                            mma16(acc[mi][ni], af[mi], bf[ni]);
                }
            }
            if (lane == 0) MBAR_ARRIVE(emptyA[st]);
            if (tid == 0 && c + STAGES < nch) issue(phase, c + STAGES, s, rp);
            if (hook && tid == 0 && c == 9) {
                while (atomicAdd(&g_pflag[tile], 0u) < (unsigned)s) { }
                __threadfence();
            }
        }
    };

    for (int s = 0; s <= 256; s++) {
        const int rp = (s + 1) & 1;

        if (layer == 0) {
            // ---- phase 0: partner layer-1 tile partial over h1[s-2] cols 256..511
            if (s >= 1) {
                run_gemm(0, 4, s, rp, false);
                float2* pp = (float2*)&g_part[(size_t)tile * 8192];
#pragma unroll
                for (int mi = 0; mi < 2; mi++) {
                    int rr = warpM * 32 + mi * 16 + (lane >> 2);
#pragma unroll
                    for (int ni = 0; ni < 4; ni++) {
                        int cc = warpN * 32 + ni * 8 + (lane & 3) * 2;
                        pp[(rr * 128 + cc) >> 1]       = make_float2(acc[mi][ni][0], acc[mi][ni][1]);
                        pp[((rr + 8) * 128 + cc) >> 1] = make_float2(acc[mi][ni][2], acc[mi][ni][3]);
                    }
                }
                __syncthreads();
                if (tid == 0) { __threadfence(); atomicExch(&g_pflag[tile], (unsigned)s); }
            }
            // ---- phase 1: own layer-0 tile
            if (s < 256) {
                run_gemm(1, 9, s, rp, false);
#pragma unroll
                for (int mi = 0; mi < 2; mi++) {
                    int rr = warpM * 32 + mi * 16 + (lane >> 2);
#pragma unroll
                    for (int ni = 0; ni < 4; ni++) {
                        int cc = warpN * 32 + ni * 8 + (lane & 3) * 2;
                        Gs[rr * 132 + cc]           = acc[mi][ni][0];
                        Gs[rr * 132 + cc + 1]       = acc[mi][ni][1];
                        Gs[(rr + 8) * 132 + cc]     = acc[mi][ni][2];
                        Gs[(rr + 8) * 132 + cc + 1] = acc[mi][ni][3];
                    }
                }
                __syncthreads();
                int r   = tid >> 2;
                int hl0 = (tid & 3) * 8;
                __half* hout = g_hA0 + (((s & 1) * 4 + mt) * 16 + strip) * 2304;
#pragma unroll
                for (int j = 0; j < 8; j++) {
                    int c4 = (hl0 + j) * 4;
                    float ip = Gs[r * 132 + c4 + 0] + bias_s[c4 + 0];
                    float fp = Gs[r * 132 + c4 + 1] + bias_s[c4 + 1];
                    float gp = Gs[r * 132 + c4 + 2] + bias_s[c4 + 2];
                    float op = Gs[r * 132 + c4 + 3] + bias_s[c4 + 3];
                    float cn = fsig(fp) * cst[j] + fsig(ip) * ftanh(gp);
                    cst[j] = cn;
                    hout[r * 36 + hl0 + j] = __float2half(fsig(op) * ftanh(cn));
                }
            }
        } else if (s >= 1) {
            // ---- layer 1: chunks 0..11 (K 0..767), partial covers K 768..1023
            run_gemm(1, 12, s, rp, true);
#pragma unroll
            for (int mi = 0; mi < 2; mi++) {
                int rr = warpM * 32 + mi * 16 + (lane >> 2);
#pragma unroll
                for (int ni = 0; ni < 4; ni++) {
                    int cc = warpN * 32 + ni * 8 + (lane & 3) * 2;
                    Gs[rr * 132 + cc]           = acc[mi][ni][0];
                    Gs[rr * 132 + cc + 1]       = acc[mi][ni][1];
                    Gs[(rr + 8) * 132 + cc]     = acc[mi][ni][2];
                    Gs[(rr + 8) * 132 + cc + 1] = acc[mi][ni][3];
                }
            }
            __syncthreads();
            int r   = tid >> 2;
            int hl0 = (tid & 3) * 8;
            const float4* pin = (const float4*)&g_part[(size_t)tile * 8192 + r * 128 + (tid & 3) * 32];
            __half* hout = g_hA1 + (((s & 1) * 4 + mt) * 16 + strip) * 2304;
#pragma unroll
            for (int j = 0; j < 8; j++) {
                int c4 = (hl0 + j) * 4;
                float4 pv = __ldcg(&pin[j]);
                float ip = Gs[r * 132 + c4 + 0] + bias_s[c4 + 0] + pv.x;
                float fp = Gs[r * 132 + c4 + 1] + bias_s[c4 + 1] + pv.y;
                float gp = Gs[r * 132 + c4 + 2] + bias_s[c4 + 2] + pv.z;
                float op = Gs[r * 132 + c4 + 3] + bias_s[c4 + 3] + pv.w;
                float cn = fsig(fp) * cst[j] + fsig(ip) * ftanh(gp);
                cst[j] = cn;
                float h = fsig(op) * ftanh(cn);
                hout[r * 36 + hl0 + j] = __float2half(h);
                if (s == 256)
                    g_h1x[(m0 + r) * 512 + strip * 32 + hl0 + j] = h;
            }
        }

        // -------- grid barrier --------
        target++;
        __threadfence();
        __syncthreads();
        if (tid == 0) {
            unsigned arrived = atomicAdd(&g_count, 1u) + 1u;
            if ((arrived & (NBLK - 1)) == 0u) {
                atomicAdd(&g_phase, 1u);
            } else {
                while (*((volatile unsigned*)&g_phase) < target) { }
            }
            __threadfence();
        }
        __syncthreads();
    }

    // -------- final FC --------
    for (int r2 = 0; r2 < 2; r2++) {
        int b = bid * 2 + r2;
        float p = 0.f;
        for (int k = tid; k < 512; k += THREADS)
            p += __ldcg(&g_h1x[b * 512 + k]) * __ldg(&Wfc[k]);
        red[tid] = p;
        __syncthreads();
        for (int off = 128; off > 0; off >>= 1) {
            if (tid < off) red[tid] += red[tid + off];
            __syncthreads();
        }
        if (tid == 0) out[b] = red[0] + __ldg(bfc);
        __syncthreads();
    }
}

// ---------------- launch --------------------------------------------------------
extern "C" void kernel_launch(void* const* d_in, const int* in_sizes, int n_in,
                              void* d_out, int out_size) {
    const float* x    = (const float*)d_in[0];
    const float* Wih0 = (const float*)d_in[1];
    const float* Whh0 = (const float*)d_in[2];
    const float* bih0 = (const float*)d_in[3];
    const float* bhh0 = (const float*)d_in[4];
    const float* Wih1 = (const float*)d_in[5];
    const float* Whh1 = (const float*)d_in[6];
    const float* bih1 = (const float*)d_in[7];
    const float* bhh1 = (const float*)d_in[8];
    const float* Wfc  = (const float*)d_in[9];
    const float* bfc  = (const float*)d_in[10];
    float* out = (float*)d_out;

    cudaFuncSetAttribute(lstm_persistent,
                         cudaFuncAttributeMaxDynamicSharedMemorySize,
                         STAGES * STAGE_BYTES + 256);

    prep_x<<<(256 * 4 * 2 * 64 * 32 + 255) / 256, 256>>>(x);
    prep_w0<<<(16 * 18 * 128 * 32 + 255) / 256, 256>>>(Wih0, Whh0);
    prep_w1<<<(16 * 32 * 128 * 32 + 255) / 256, 256>>>(Wih1, Whh1);
    prep_bias<<<(4096 + 255) / 256, 256>>>(bih0, bhh0, bih1, bhh1);
    prep_zero<<<(2 * 4 * 16 * 2304 + 255) / 256, 256>>>();
    lstm_persistent<<<NBLK, THREADS, STAGES * STAGE_BYTES + 256>>>(Wfc, bfc, out);
}

// round 8
// speedup vs baseline: 2.6928x; 1.1455x over previous
#include <cuda_runtime.h>
#include <cuda_fp16.h>
#include <cstdint>

#define NBLK    128
#define THREADS 256
#define STAGES  4
#define A_BYTES 10240          // 2 K32 A-blocks of 64 rows x 40 halves
#define B_BYTES 20480          // 2 K32 B-blocks of 128 rows x 40 halves
#define STAGE_BYTES 30720

// ---------------- device globals: fp16 pre-packed tile images (stride 40) ---
__device__ __half g_xA[256 * 4 * 2 * 2560];     // [t][mt][kc] A-blocks
__device__ __half g_hA0[2 * 4 * 16 * 2560];     // [par][mt][strip]
__device__ __half g_hA1[2 * 4 * 16 * 2560];
__device__ __half g_Bp0[16 * 18 * 5120];        // [strip][kt32] B-blocks
__device__ __half g_Bp1[16 * 32 * 5120];
__device__ float g_bias0[16 * 128];
__device__ float g_bias1[16 * 128];
__device__ float g_part[64 * 8192];             // per-tile fp32 gate partials
__device__ unsigned g_pflag[64];
__device__ float g_h1x[256 * 512];
__device__ unsigned g_cnt[4 * 32];              // per-mt group barrier (padded lines)
__device__ unsigned g_phs[4 * 32];

// ---------------- helpers ----------------------------------------------------
__device__ __forceinline__ uint32_t smem_u32(const void* p) {
    uint32_t a;
    asm("{ .reg .u64 t; cvta.to.shared.u64 t, %1; cvt.u32.u64 %0, t; }" : "=r"(a) : "l"(p));
    return a;
}
__device__ __forceinline__ unsigned ld_acq(const unsigned* p) {
    unsigned v;
    asm volatile("ld.acquire.gpu.global.b32 %0, [%1];" : "=r"(v) : "l"(p) : "memory");
    return v;
}
__device__ __forceinline__ unsigned atom_add_acqrel(unsigned* p, unsigned v) {
    unsigned o;
    asm volatile("atom.add.acq_rel.gpu.global.u32 %0, [%1], %2;" : "=r"(o) : "l"(p), "r"(v) : "memory");
    return o;
}
__device__ __forceinline__ void st_rel(unsigned* p, unsigned v) {
    asm volatile("st.release.gpu.global.b32 [%0], %1;" :: "l"(p), "r"(v) : "memory");
}
#define MBAR_INIT(a, n) \
    asm volatile("mbarrier.init.shared.b64 [%0], %1;" :: "r"(a), "r"((uint32_t)(n)) : "memory")
#define MBAR_EXPECT_TX(a, b) \
    asm volatile("mbarrier.arrive.expect_tx.shared.b64 _, [%0], %1;" :: "r"(a), "r"((uint32_t)(b)) : "memory")
#define MBAR_ARRIVE(a) \
    asm volatile("mbarrier.arrive.shared.b64 _, [%0];" :: "r"(a) : "memory")
#define MBAR_WAIT(a, p) do {                                                               \
    asm volatile("{\n\t.reg .pred P1;\n\t"                                                 \
        "WL_%=:\n\t"                                                                       \
        "mbarrier.try_wait.parity.acquire.cta.shared::cta.b64 P1, [%0], %1, 0x989680;\n\t" \
        "@P1 bra.uni WD_%=;\n\t"                                                           \
        "bra.uni WL_%=;\n\t"                                                               \
        "WD_%=:\n\t}"                                                                      \
        :: "r"(a), "r"((uint32_t)(p)) : "memory");                                         \
} while (0)
#define BULK_G2S(dst, src, bytes, mbar)                                                    \
    asm volatile("cp.async.bulk.shared::cluster.global.mbarrier::complete_tx::bytes "      \
                 "[%0], [%1], %2, [%3];"                                                   \
        :: "r"(dst), "l"(src), "r"((uint32_t)(bytes)), "r"(mbar) : "memory")

__device__ __forceinline__ void mma16(float* c, const uint32_t* a, const uint32_t* b) {
    asm volatile(
        "mma.sync.aligned.m16n8k16.row.col.f32.f16.f16.f32 "
        "{%0,%1,%2,%3},{%4,%5,%6,%7},{%8,%9},{%0,%1,%2,%3};"
        : "+f"(c[0]), "+f"(c[1]), "+f"(c[2]), "+f"(c[3])
        : "r"(a[0]), "r"(a[1]), "r"(a[2]), "r"(a[3]), "r"(b[0]), "r"(b[1]));
}
__device__ __forceinline__ float fsig(float x) { return 1.f / (1.f + __expf(-x)); }
__device__ __forceinline__ float ftanh(float x) { return 1.f - 2.f / (__expf(2.f * x) + 1.f); }
__device__ __forceinline__ uint32_t pk2(float a, float b) {
    __half2 h = __floats2half2_rn(a, b);
    return *(uint32_t*)&h;
}

// ---------------- prep kernels (3 launches) -----------------------------------
__global__ void prep_x(const float* __restrict__ x) {
    int idx = blockIdx.x * blockDim.x + threadIdx.x;
    if (idx >= 256 * 4 * 2 * 64 * 32) return;
    int kk = idx & 31;
    int r  = (idx >> 5) & 63;
    int kc = (idx >> 11) & 1;
    int mt = (idx >> 12) & 3;
    int t  = idx >> 14;
    int b = mt * 64 + r, d = kc * 32 + kk;
    g_xA[(size_t)((t * 4 + mt) * 2 + kc) * 2560 + r * 40 + kk] =
        __float2half(x[(b * 256 + t) * 64 + d]);
}
__global__ void prep_w(const float* __restrict__ Wih0, const float* __restrict__ Whh0,
                       const float* __restrict__ bih0, const float* __restrict__ bhh0,
                       const float* __restrict__ Wih1, const float* __restrict__ Whh1,
                       const float* __restrict__ bih1, const float* __restrict__ bhh1) {
    int idx = blockIdx.x * blockDim.x + threadIdx.x;
    const int NW0 = 16 * 18 * 128 * 32;
    const int NW1 = 16 * 32 * 128 * 32;
    if (idx < NW0) {
        int kk = idx & 31;
        int n  = (idx >> 5) & 127;
        int kt = (idx >> 12) % 18;
        int nt = idx / (18 * 4096);
        int row = (n & 3) * 512 + nt * 32 + (n >> 2);
        int k = kt * 32 + kk;
        float v = (k < 64) ? Wih0[row * 64 + k] : Whh0[row * 512 + (k - 64)];
        g_Bp0[(size_t)(nt * 18 + kt) * 5120 + n * 40 + kk] = __float2half(v);
    } else if (idx < NW0 + NW1) {
        int j = idx - NW0;
        int kk = j & 31;
        int n  = (j >> 5) & 127;
        int kt = (j >> 12) & 31;
        int nt = j >> 17;
        int row = (n & 3) * 512 + nt * 32 + (n >> 2);
        int k = kt * 32 + kk;
        float v = (k < 512) ? Wih1[row * 512 + k] : Whh1[row * 512 + (k - 512)];
        g_Bp1[(size_t)(nt * 32 + kt) * 5120 + n * 40 + kk] = __float2half(v);
    } else if (idx < NW0 + NW1 + 2 * 2048) {
        int j = idx - NW0 - NW1;
        int l = j >> 11;
        int rr = j & 2047;
        int c = rr & 127, nt = rr >> 7;
        int row = (c & 3) * 512 + nt * 32 + (c >> 2);
        float v = l ? (bih1[row] + bhh1[row]) : (bih0[row] + bhh0[row]);
        (l ? g_bias1 : g_bias0)[rr] = v;
    }
}
__global__ void prep_zero() {
    int idx = blockIdx.x * blockDim.x + threadIdx.x;
    if (idx < 2 * 4 * 16 * 2560) {
        g_hA0[idx] = __float2half(0.f);
        g_hA1[idx] = __float2half(0.f);
    }
    if (idx < 64) g_pflag[idx] = 0u;
    if (idx < 128) { g_cnt[idx] = 0u; g_phs[idx] = 0u; }
}

// ---------------- persistent LSTM kernel ---------------------------------------
__global__ __launch_bounds__(THREADS, 1)
void lstm_persistent(const float* __restrict__ Wfc, const float* __restrict__ bfc,
                     float* __restrict__ out) {
    extern __shared__ char dsm_raw[];
    __shared__ __align__(8) unsigned long long mb_full[STAGES], mb_empty[STAGES];
    __shared__ float Gs[64 * 132];
    __shared__ float bias_s[128];
    __shared__ float red[THREADS];

    const int tid   = threadIdx.x;
    const int lane  = tid & 31;
    const int warp  = tid >> 5;
    const int warpM = warp >> 2;
    const int warpN = warp & 3;
    const int bid   = blockIdx.x;
    const int layer = bid >> 6;
    const int tile  = bid & 63;
    const int mt    = tile & 3;
    const int strip = tile >> 2;

    uint32_t rawu  = smem_u32(dsm_raw);
    uint32_t dsm_u = (rawu + 127u) & ~127u;
    char* sbase = dsm_raw + (dsm_u - rawu);
    uint32_t fullA[STAGES], emptyA[STAGES], aS[STAGES];
#pragma unroll
    for (int s = 0; s < STAGES; s++) {
        aS[s] = dsm_u + s * STAGE_BYTES;
        fullA[s]  = smem_u32(&mb_full[s]);
        emptyA[s] = smem_u32(&mb_empty[s]);
    }
    if (tid == 0) {
#pragma unroll
        for (int s = 0; s < STAGES; s++) { MBAR_INIT(fullA[s], 1); MBAR_INIT(emptyA[s], 8); }
    }
    for (int i = tid; i < 128; i += THREADS)
        bias_s[i] = ((layer ? g_bias1 : g_bias0) + strip * 128)[i];
    __syncthreads();

    float cst[8];
#pragma unroll
    for (int j = 0; j < 8; j++) cst[j] = 0.f;
    float acc[2][4][4];

    int p_st = 0, p_ph = 1;
    int c_st = 0, c_ph = 0;
    unsigned target = 0;
    int pidx = 0, s_cur = 0, rp_cur = 0;

    // issue chunk c of the current step (tid 0 only)
    auto issue = [&](int c) {
        const __half* a;
        const __half* b;
        if (layer == 0) {
            if (c < pidx) {
                a = g_hA1 + (size_t)((rp_cur * 4 + mt) * 16 + 8 + 2 * c) * 2560;
                b = g_Bp1 + (size_t)(strip * 32 + 24 + 2 * c) * 5120;
            } else {
                int j = c - pidx;
                a = (j == 0) ? g_xA + (size_t)((s_cur * 4 + mt) * 2) * 2560
                             : g_hA0 + (size_t)((rp_cur * 4 + mt) * 16 + (j - 1) * 2) * 2560;
                b = g_Bp0 + (size_t)(strip * 18 + 2 * j) * 5120;
            }
        } else {
            a = (c < 8) ? g_hA0 + (size_t)((rp_cur * 4 + mt) * 16 + 2 * c) * 2560
                        : g_hA1 + (size_t)((rp_cur * 4 + mt) * 16 + (2 * c - 16)) * 2560;
            b = g_Bp1 + (size_t)(strip * 32 + 2 * c) * 5120;
        }
        MBAR_WAIT(emptyA[p_st], p_ph);
        MBAR_EXPECT_TX(fullA[p_st], STAGE_BYTES);
        BULK_G2S(aS[p_st], a, A_BYTES, fullA[p_st]);
        BULK_G2S(aS[p_st] + A_BYTES, b, B_BYTES, fullA[p_st]);
        if (++p_st == STAGES) { p_st = 0; p_ph ^= 1; }
    };

    for (int s = 0; s <= 256; s++) {
        const int rp = (s + 1) & 1;
        s_cur = s; rp_cur = rp;
        pidx = (layer == 0 && s >= 1) ? 4 : 0;
        int nch;
        if (layer == 0) nch = pidx + (s < 256 ? 9 : 0);
        else            nch = (s >= 1) ? 12 : 0;

        if (nch > 0) {
#pragma unroll
            for (int mi = 0; mi < 2; mi++)
#pragma unroll
                for (int ni = 0; ni < 4; ni++)
#pragma unroll
                    for (int q = 0; q < 4; q++) acc[mi][ni][q] = 0.f;

            if (tid == 0) {
                int pre = nch < STAGES ? nch : STAGES;
                for (int i = 0; i < pre; i++) issue(i);
            }

            for (int c = 0; c < nch; c++) {
                int st = c_st;
                MBAR_WAIT(fullA[st], c_ph);
                if (++c_st == STAGES) { c_st = 0; c_ph ^= 1; }

                const uint32_t* stW = (const uint32_t*)(sbase + st * STAGE_BYTES);
#pragma unroll
                for (int sub = 0; sub < 2; sub++) {
                    const uint32_t* aw = stW + sub * 1280;
                    const uint32_t* bw = stW + 2560 + sub * 2560;
#pragma unroll
                    for (int kk = 0; kk < 2; kk++) {
                        uint32_t af[2][4], bf[4][2];
#pragma unroll
                        for (int mi = 0; mi < 2; mi++) {
                            int rb = warpM * 32 + mi * 16 + (lane >> 2);
                            int wi = rb * 20 + (lane & 3) + kk * 8;
                            af[mi][0] = aw[wi];
                            af[mi][1] = aw[wi + 160];
                            af[mi][2] = aw[wi + 4];
                            af[mi][3] = aw[wi + 164];
                        }
#pragma unroll
                        for (int ni = 0; ni < 4; ni++) {
                            int nb = warpN * 32 + ni * 8 + (lane >> 2);
                            int wi = nb * 20 + (lane & 3) + kk * 8;
                            bf[ni][0] = bw[wi];
                            bf[ni][1] = bw[wi + 4];
                        }
#pragma unroll
                        for (int mi = 0; mi < 2; mi++)
#pragma unroll
                            for (int ni = 0; ni < 4; ni++)
                                mma16(acc[mi][ni], af[mi], bf[ni]);
                    }
                }
                if (lane == 0) MBAR_ARRIVE(emptyA[st]);
                if (tid == 0 && c + STAGES < nch) issue(c + STAGES);

                if (layer == 0 && pidx && c == pidx - 1) {
                    // dump layer-1 partial (regs -> gmem), release flag, reset acc
                    float2* pp = (float2*)&g_part[(size_t)tile * 8192];
#pragma unroll
                    for (int mi = 0; mi < 2; mi++) {
                        int rr = warpM * 32 + mi * 16 + (lane >> 2);
#pragma unroll
                        for (int ni = 0; ni < 4; ni++) {
                            int cc = warpN * 32 + ni * 8 + (lane & 3) * 2;
                            pp[(rr * 128 + cc) >> 1]       = make_float2(acc[mi][ni][0], acc[mi][ni][1]);
                            pp[((rr + 8) * 128 + cc) >> 1] = make_float2(acc[mi][ni][2], acc[mi][ni][3]);
                        }
                    }
                    __syncthreads();
                    if (tid == 0) st_rel(&g_pflag[tile], (unsigned)s);
#pragma unroll
                    for (int mi = 0; mi < 2; mi++)
#pragma unroll
                        for (int ni = 0; ni < 4; ni++)
#pragma unroll
                            for (int q = 0; q < 4; q++) acc[mi][ni][q] = 0.f;
                }
                if (layer == 1 && c == 9 && tid == 0) {
                    while (ld_acq(&g_pflag[tile]) < (unsigned)s) { }
                }
            }

            // ---- epilogue (skip for layer-0 at s==256: partial only) ----
            bool do_epi = (layer == 1) || (s < 256);
            if (do_epi) {
#pragma unroll
                for (int mi = 0; mi < 2; mi++) {
                    int rr = warpM * 32 + mi * 16 + (lane >> 2);
#pragma unroll
                    for (int ni = 0; ni < 4; ni++) {
                        int cc = warpN * 32 + ni * 8 + (lane & 3) * 2;
                        Gs[rr * 132 + cc]           = acc[mi][ni][0];
                        Gs[rr * 132 + cc + 1]       = acc[mi][ni][1];
                        Gs[(rr + 8) * 132 + cc]     = acc[mi][ni][2];
                        Gs[(rr + 8) * 132 + cc + 1] = acc[mi][ni][3];
                    }
                }
                __syncthreads();

                int r   = tid >> 2;
                int hl0 = (tid & 3) * 8;
                float hv[8];
                if (layer == 0) {
#pragma unroll
                    for (int j = 0; j < 8; j++) {
                        int c4 = (hl0 + j) * 4;
                        float ip = Gs[r * 132 + c4 + 0] + bias_s[c4 + 0];
                        float fp = Gs[r * 132 + c4 + 1] + bias_s[c4 + 1];
                        float gp = Gs[r * 132 + c4 + 2] + bias_s[c4 + 2];
                        float op = Gs[r * 132 + c4 + 3] + bias_s[c4 + 3];
                        float cn = fsig(fp) * cst[j] + fsig(ip) * ftanh(gp);
                        cst[j] = cn;
                        hv[j] = fsig(op) * ftanh(cn);
                    }
                    __half* hout = g_hA0 + (size_t)(((s & 1) * 4 + mt) * 16 + strip) * 2560;
                    uint4 v = { pk2(hv[0], hv[1]), pk2(hv[2], hv[3]),
                                pk2(hv[4], hv[5]), pk2(hv[6], hv[7]) };
                    *(uint4*)(&hout[r * 40 + hl0]) = v;
                } else {
                    const float4* pin =
                        (const float4*)&g_part[(size_t)tile * 8192 + r * 128 + (tid & 3) * 32];
#pragma unroll
                    for (int j = 0; j < 8; j++) {
                        int c4 = (hl0 + j) * 4;
                        float4 pv = __ldcg(&pin[j]);
                        float ip = Gs[r * 132 + c4 + 0] + bias_s[c4 + 0] + pv.x;
                        float fp = Gs[r * 132 + c4 + 1] + bias_s[c4 + 1] + pv.y;
                        float gp = Gs[r * 132 + c4 + 2] + bias_s[c4 + 2] + pv.z;
                        float op = Gs[r * 132 + c4 + 3] + bias_s[c4 + 3] + pv.w;
                        float cn = fsig(fp) * cst[j] + fsig(ip) * ftanh(gp);
                        cst[j] = cn;
                        hv[j] = fsig(op) * ftanh(cn);
                    }
                    __half* hout = g_hA1 + (size_t)(((s & 1) * 4 + mt) * 16 + strip) * 2560;
                    uint4 v = { pk2(hv[0], hv[1]), pk2(hv[2], hv[3]),
                                pk2(hv[4], hv[5]), pk2(hv[6], hv[7]) };
                    *(uint4*)(&hout[r * 40 + hl0]) = v;
                    if (s == 256) {
#pragma unroll
                        for (int j = 0; j < 8; j++)
                            g_h1x[(mt * 64 + r) * 512 + strip * 32 + hl0 + j] = hv[j];
                    }
                }
            }
        }

        // -------- per-mt group barrier (32 CTAs) --------
        target++;
        __syncthreads();
        if (tid == 0) {
            unsigned a = atom_add_acqrel(&g_cnt[mt << 5], 1u) + 1u;
            if (a == target * 32u) st_rel(&g_phs[mt << 5], target);
            else while (ld_acq(&g_phs[mt << 5]) < target) { }
        }
        __syncthreads();
    }

    // -------- final FC: rows mt*64 + 2*gidx + {0,1} --------
    int gidx = layer ? (16 + strip) : strip;
    for (int r2 = 0; r2 < 2; r2++) {
        int b = mt * 64 + 2 * gidx + r2;
        float p = 0.f;
        for (int k = tid; k < 512; k += THREADS)
            p += __ldcg(&g_h1x[b * 512 + k]) * __ldg(&Wfc[k]);
        red[tid] = p;
        __syncthreads();
        for (int off = 128; off > 0; off >>= 1) {
            if (tid < off) red[tid] += red[tid + off];
            __syncthreads();
        }
        if (tid == 0) out[b] = red[0] + __ldg(bfc);
        __syncthreads();
    }
}

// ---------------- launch --------------------------------------------------------
extern "C" void kernel_launch(void* const* d_in, const int* in_sizes, int n_in,
                              void* d_out, int out_size) {
    const float* x    = (const float*)d_in[0];
    const float* Wih0 = (const float*)d_in[1];
    const float* Whh0 = (const float*)d_in[2];
    const float* bih0 = (const float*)d_in[3];
    const float* bhh0 = (const float*)d_in[4];
    const float* Wih1 = (const float*)d_in[5];
    const float* Whh1 = (const float*)d_in[6];
    const float* bih1 = (const float*)d_in[7];
    const float* bhh1 = (const float*)d_in[8];
    const float* Wfc  = (const float*)d_in[9];
    const float* bfc  = (const float*)d_in[10];
    float* out = (float*)d_out;

    cudaFuncSetAttribute(lstm_persistent,
                         cudaFuncAttributeMaxDynamicSharedMemorySize,
                         STAGES * STAGE_BYTES + 256);

    prep_x<<<(256 * 4 * 2 * 64 * 32 + 255) / 256, 256>>>(x);
    int wtot = 16 * 18 * 128 * 32 + 16 * 32 * 128 * 32 + 2 * 2048;
    prep_w<<<(wtot + 255) / 256, 256>>>(Wih0, Whh0, bih0, bhh0, Wih1, Whh1, bih1, bhh1);
    prep_zero<<<(2 * 4 * 16 * 2560 + 255) / 256, 256>>>();
    lstm_persistent<<<NBLK, THREADS, STAGES * STAGE_BYTES + 256>>>(Wfc, bfc, out);
}